// round 1
// baseline (speedup 1.0000x reference)
#include <cuda_runtime.h>
#include <math.h>

#define B_  4
#define T_  2048
#define D_  1024
#define NH_ 16
#define HS_ 64
#define NBIAS (2*T_ - 1)   // 4095

// ---------------- scratch (device globals: no allocation allowed) ----------
__device__ float g_Q [B_*NH_*T_*HS_];   // 33.5 MB  [b,h,t,hs]
__device__ float g_K [B_*NH_*T_*HS_];
__device__ float g_V [B_*NH_*T_*HS_];
__device__ float g_AO[B_*T_*D_];        // attention output, [b,t,d]
__device__ float g_bias[NH_*NBIAS];     // bias table per head per relative pos

// ---------------- bias table --------------------------------------------
__device__ __forceinline__ int bucket_of(int rp) {
    // T5 bidirectional bucketing, n_buckets=32, max_distance=128
    int b = (rp > 0) ? 16 : 0;
    int a = rp < 0 ? -rp : rp;
    if (a < 8) return b + a;
    // me=7, nbm=15: large = 7 + trunc(log(a/7)/log(128/7)*8), clamped to 15
    double v = 7.0 + (log((double)a / 7.0) / log(128.0 / 7.0)) * 8.0;
    int large = (int)v;           // trunc toward zero (matches astype(int32))
    if (large > 15) large = 15;
    return b + large;
}

__global__ void bias_kernel(const float* __restrict__ rel_emb, float* __restrict__ btab) {
    int idx = blockIdx.x * blockDim.x + threadIdx.x;
    if (idx >= NH_ * NBIAS) return;
    int h = idx / NBIAS;
    int x = idx % NBIAS;
    int rp = x - (T_ - 1);                  // rp = k - q in [-2047, 2047]
    btab[idx] = rel_emb[bucket_of(rp) * NH_ + h];
}

// ---------------- SGEMM: out[m,n] = sum_k A[m,k] * W[n,k]  (NT) -----------
// M=8192, N=1024, K=1024. Tile 128x128x16, 256 threads, 8x8 per thread.
// MODE 0: out remapped to [b,h,t,hs] ; MODE 1: plain row-major [m,n].
template <int MODE>
__global__ __launch_bounds__(256, 2)
void gemm_nt(const float* __restrict__ A, const float* __restrict__ W,
             float* __restrict__ out) {
    __shared__ float As[16 * 128];   // k-major: As[k][m]
    __shared__ float Bs[16 * 128];   // k-major: Bs[k][n]

    const int tid = threadIdx.x;
    const int ty = tid >> 4;         // 0..15 -> m sub-rows
    const int tx = tid & 15;         // 0..15 -> n sub-cols
    const int m0 = blockIdx.y * 128;
    const int n0 = blockIdx.x * 128;

    const int lr = tid & 127;        // load row within tile
    const int lk = tid >> 7;         // 0..1

    float c[8][8];
#pragma unroll
    for (int i = 0; i < 8; i++)
#pragma unroll
        for (int j = 0; j < 8; j++) c[i][j] = 0.f;

    for (int k0 = 0; k0 < 1024; k0 += 16) {
        __syncthreads();
        // load + transpose 128x16 tiles of A and W (conflict-free STS: bank = lr%32)
#pragma unroll
        for (int s = 0; s < 2; s++) {
            int kk = lk + 2 * s;     // 0..3 (group of 4 k's)
            float4 va = *(const float4*)(A + (m0 + lr) * 1024 + k0 + 4 * kk);
            As[(4 * kk + 0) * 128 + lr] = va.x;
            As[(4 * kk + 1) * 128 + lr] = va.y;
            As[(4 * kk + 2) * 128 + lr] = va.z;
            As[(4 * kk + 3) * 128 + lr] = va.w;
            float4 vb = *(const float4*)(W + (n0 + lr) * 1024 + k0 + 4 * kk);
            Bs[(4 * kk + 0) * 128 + lr] = vb.x;
            Bs[(4 * kk + 1) * 128 + lr] = vb.y;
            Bs[(4 * kk + 2) * 128 + lr] = vb.z;
            Bs[(4 * kk + 3) * 128 + lr] = vb.w;
        }
        __syncthreads();
#pragma unroll
        for (int k = 0; k < 16; k++) {
            float a[8], b[8];
            *(float4*)(a)     = *(const float4*)(As + k * 128 + 8 * ty);
            *(float4*)(a + 4) = *(const float4*)(As + k * 128 + 8 * ty + 4);
            *(float4*)(b)     = *(const float4*)(Bs + k * 128 + 8 * tx);
            *(float4*)(b + 4) = *(const float4*)(Bs + k * 128 + 8 * tx + 4);
#pragma unroll
            for (int i = 0; i < 8; i++)
#pragma unroll
                for (int j = 0; j < 8; j++) c[i][j] += a[i] * b[j];
        }
    }

#pragma unroll
    for (int i = 0; i < 8; i++) {
        int m = m0 + 8 * ty + i;
        if (MODE == 0) {
            int b = m >> 11, t = m & (T_ - 1);
#pragma unroll
            for (int jg = 0; jg < 8; jg += 4) {
                int n = n0 + 8 * tx + jg;
                int h = n >> 6, hs = n & 63;
                float4 v = make_float4(c[i][jg], c[i][jg + 1], c[i][jg + 2], c[i][jg + 3]);
                *(float4*)(out + ((b * NH_ + h) * T_ + t) * HS_ + hs) = v;
            }
        } else {
#pragma unroll
            for (int jg = 0; jg < 8; jg += 4) {
                float4 v = make_float4(c[i][jg], c[i][jg + 1], c[i][jg + 2], c[i][jg + 3]);
                *(float4*)(out + m * 1024 + n0 + 8 * tx + jg) = v;
            }
        }
    }
}

// ---------------- fused flash attention (fp32) ----------------------------
// Per CTA: one (b,h) and a 64-row q tile. Stream 64-col k tiles, online softmax.
// 256 threads as 16x16; thread (ty,tx) owns S/O sub-tile rows 4ty.., cols 4tx..
__global__ __launch_bounds__(256, 2)
void attn_kernel(const float* __restrict__ Q, const float* __restrict__ K,
                 const float* __restrict__ V, const float* __restrict__ btab,
                 float* __restrict__ out) {
    __shared__ float Qs [64 * 64];   // k-major: Qs[d][r]
    __shared__ float KPs[64 * 64];   // K tile (k-major: [d][c]) then aliased as swizzled P
    __shared__ float Vs [64 * 64];   // Vs[kk][c]   (c = hs)

    const int tid = threadIdx.x;
    const int ty = tid >> 4;
    const int tx = tid & 15;
    const int bh = blockIdx.y;              // b*NH + h
    const int h  = bh & (NH_ - 1);
    const int b  = bh >> 4;
    const int q0 = blockIdx.x * 64;

    const float* Qb = Q + (size_t)bh * T_ * HS_;
    const float* Kb = K + (size_t)bh * T_ * HS_;
    const float* Vb = V + (size_t)bh * T_ * HS_;

    // load Q tile, transposed + pre-scaled by 1/sqrt(64)
#pragma unroll
    for (int s = 0; s < 4; s++) {
        int f = tid + s * 256;
        int r = f & 63, dg = f >> 6;
        float4 v = *(const float4*)(Qb + (q0 + r) * HS_ + 4 * dg);
        Qs[(4 * dg + 0) * 64 + r] = v.x * 0.125f;
        Qs[(4 * dg + 1) * 64 + r] = v.y * 0.125f;
        Qs[(4 * dg + 2) * 64 + r] = v.z * 0.125f;
        Qs[(4 * dg + 3) * 64 + r] = v.w * 0.125f;
    }

    float o[4][4];
    float m_r[4], l_r[4];
#pragma unroll
    for (int i = 0; i < 4; i++) {
        m_r[i] = -1e30f; l_r[i] = 0.f;
#pragma unroll
        for (int j = 0; j < 4; j++) o[i][j] = 0.f;
    }

    for (int k0 = 0; k0 < T_; k0 += 64) {
        __syncthreads();   // prior iter done reading KPs/Vs
        // K tile transposed
#pragma unroll
        for (int s = 0; s < 4; s++) {
            int f = tid + s * 256;
            int r = f & 63, dg = f >> 6;
            float4 v = *(const float4*)(Kb + (k0 + r) * HS_ + 4 * dg);
            KPs[(4 * dg + 0) * 64 + r] = v.x;
            KPs[(4 * dg + 1) * 64 + r] = v.y;
            KPs[(4 * dg + 2) * 64 + r] = v.z;
            KPs[(4 * dg + 3) * 64 + r] = v.w;
        }
        // V tile direct (coalesced)
#pragma unroll
        for (int s = 0; s < 4; s++) {
            int f = tid + s * 256;
            int kk = f >> 4, cg = f & 15;
            *(float4*)(Vs + kk * 64 + 4 * cg) =
                *(const float4*)(Vb + (k0 + kk) * HS_ + 4 * cg);
        }
        __syncthreads();

        // S = (Q/8) K^T
        float s_[4][4];
#pragma unroll
        for (int i = 0; i < 4; i++)
#pragma unroll
            for (int j = 0; j < 4; j++) s_[i][j] = 0.f;
#pragma unroll 16
        for (int d = 0; d < 64; d++) {
            float4 a  = *(const float4*)(Qs  + d * 64 + 4 * ty);
            float4 bb = *(const float4*)(KPs + d * 64 + 4 * tx);
            s_[0][0] += a.x * bb.x; s_[0][1] += a.x * bb.y; s_[0][2] += a.x * bb.z; s_[0][3] += a.x * bb.w;
            s_[1][0] += a.y * bb.x; s_[1][1] += a.y * bb.y; s_[1][2] += a.y * bb.z; s_[1][3] += a.y * bb.w;
            s_[2][0] += a.z * bb.x; s_[2][1] += a.z * bb.y; s_[2][2] += a.z * bb.z; s_[2][3] += a.z * bb.w;
            s_[3][0] += a.w * bb.x; s_[3][1] += a.w * bb.y; s_[3][2] += a.w * bb.z; s_[3][3] += a.w * bb.w;
        }

        // + relative-position bias (L1-hot 512B table slice)
        const float* bp = btab + h * NBIAS + (T_ - 1) + (k0 + 4 * tx) - (q0 + 4 * ty);
#pragma unroll
        for (int i = 0; i < 4; i++)
#pragma unroll
            for (int j = 0; j < 4; j++) s_[i][j] += bp[j - i];

        // online softmax: row max across the 16-lane row group
        float mt[4];
#pragma unroll
        for (int i = 0; i < 4; i++)
            mt[i] = fmaxf(fmaxf(s_[i][0], s_[i][1]), fmaxf(s_[i][2], s_[i][3]));
#pragma unroll
        for (int off = 8; off; off >>= 1)
#pragma unroll
            for (int i = 0; i < 4; i++)
                mt[i] = fmaxf(mt[i], __shfl_xor_sync(0xffffffffu, mt[i], off));

        float alpha[4];
#pragma unroll
        for (int i = 0; i < 4; i++) {
            float mn = fmaxf(m_r[i], mt[i]);
            alpha[i] = __expf(m_r[i] - mn);
            m_r[i] = mn;
        }
        float ls[4];
#pragma unroll
        for (int i = 0; i < 4; i++) {
            ls[i] = 0.f;
#pragma unroll
            for (int j = 0; j < 4; j++) {
                float p = __expf(s_[i][j] - m_r[i]);
                s_[i][j] = p;
                ls[i] += p;
            }
        }
#pragma unroll
        for (int off = 8; off; off >>= 1)
#pragma unroll
            for (int i = 0; i < 4; i++)
                ls[i] += __shfl_xor_sync(0xffffffffu, ls[i], off);
#pragma unroll
        for (int i = 0; i < 4; i++) {
            l_r[i] = l_r[i] * alpha[i] + ls[i];
#pragma unroll
            for (int j = 0; j < 4; j++) o[i][j] *= alpha[i];
        }

        __syncthreads();   // everyone finished reading K from KPs
        // write P into KPs, XOR-swizzled: element (r=4ty+i, c=4tx+j)
        // stored at KPs[c][ ((ty ^ (c>>2)) << 2) + i ] ; here c>>2 == tx
#pragma unroll
        for (int j = 0; j < 4; j++) {
            float4 v = make_float4(s_[0][j], s_[1][j], s_[2][j], s_[3][j]);
            *(float4*)(KPs + (4 * tx + j) * 64 + ((ty ^ tx) << 2)) = v;
        }
        __syncthreads();

        // O += P * V
#pragma unroll 16
        for (int kk = 0; kk < 64; kk++) {
            int g = (kk >> 2) & 15;
            float4 a  = *(const float4*)(KPs + kk * 64 + ((ty ^ g) << 2));
            float4 bb = *(const float4*)(Vs + kk * 64 + 4 * tx);
            o[0][0] += a.x * bb.x; o[0][1] += a.x * bb.y; o[0][2] += a.x * bb.z; o[0][3] += a.x * bb.w;
            o[1][0] += a.y * bb.x; o[1][1] += a.y * bb.y; o[1][2] += a.y * bb.z; o[1][3] += a.y * bb.w;
            o[2][0] += a.z * bb.x; o[2][1] += a.z * bb.y; o[2][2] += a.z * bb.z; o[2][3] += a.z * bb.w;
            o[3][0] += a.w * bb.x; o[3][1] += a.w * bb.y; o[3][2] += a.w * bb.z; o[3][3] += a.w * bb.w;
        }
    }

    // epilogue: normalize, write [b, t, h*64+hs]
#pragma unroll
    for (int i = 0; i < 4; i++) {
        float inv = 1.0f / l_r[i];
        int t = q0 + 4 * ty + i;
        float4 v = make_float4(o[i][0] * inv, o[i][1] * inv, o[i][2] * inv, o[i][3] * inv);
        *(float4*)(out + (size_t)(b * T_ + t) * D_ + h * HS_ + 4 * tx) = v;
    }
}

// ---------------- launch ---------------------------------------------------
extern "C" void kernel_launch(void* const* d_in, const int* in_sizes, int n_in,
                              void* d_out, int out_size) {
    const float* queries = (const float*)d_in[0];
    const float* Wq      = (const float*)d_in[1];
    const float* Wk      = (const float*)d_in[2];
    const float* Wv      = (const float*)d_in[3];
    const float* Wo      = (const float*)d_in[4];
    const float* rel_emb = (const float*)d_in[5];
    float* out = (float*)d_out;

    float *gQ, *gK, *gV, *gAO, *gB;
    cudaGetSymbolAddress((void**)&gQ,  g_Q);
    cudaGetSymbolAddress((void**)&gK,  g_K);
    cudaGetSymbolAddress((void**)&gV,  g_V);
    cudaGetSymbolAddress((void**)&gAO, g_AO);
    cudaGetSymbolAddress((void**)&gB,  g_bias);

    // 1) bias table
    bias_kernel<<<(NH_ * NBIAS + 255) / 256, 256>>>(rel_emb, gB);

    // 2) Q/K/V projections (NT gemm, output remapped to [b,h,t,hs])
    dim3 gGrid(1024 / 128, (B_ * T_) / 128);   // (8, 64)
    gemm_nt<0><<<gGrid, 256>>>(queries, Wq, gQ);
    gemm_nt<0><<<gGrid, 256>>>(queries, Wk, gK);
    gemm_nt<0><<<gGrid, 256>>>(queries, Wv, gV);

    // 3) fused attention with bias + online softmax
    dim3 aGrid(T_ / 64, B_ * NH_);             // (32, 64)
    attn_kernel<<<aGrid, 256>>>(gQ, gK, gV, gB, gAO);

    // 4) output projection
    gemm_nt<1><<<gGrid, 256>>>(gAO, Wo, out);
}

// round 3
// speedup vs baseline: 1.2865x; 1.2865x over previous
#include <cuda_runtime.h>
#include <cuda_bf16.h>
#include <math.h>
#include <stdint.h>

#define B_  4
#define T_  2048
#define D_  1024
#define NH_ 16
#define HS_ 64
#define NBIAS (2*T_ - 1)   // 4095
#define M_  (B_*T_)        // 8192
#define K3_ 3072           // split-bf16 K: [hi | hi | lo] x [hi | lo | hi]

// ---------------- scratch (device globals: no allocation allowed) ----------
__device__ __nv_bfloat16 g_A3 [M_*(size_t)K3_];    // queries split
__device__ __nv_bfloat16 g_AO3[M_*(size_t)K3_];    // attn-out split
__device__ __nv_bfloat16 g_W3 [4*(size_t)D_*K3_];  // 4 weights split
__device__ float g_Q [M_*(size_t)D_];              // row-major [b*t, d]
__device__ float g_K [M_*(size_t)D_];
__device__ float g_V [M_*(size_t)D_];
__device__ float g_AO[M_*(size_t)D_];
__device__ float g_bias[NH_*NBIAS];

// ============================ PTX helpers ==================================
__device__ __forceinline__ uint32_t smem_u32(const void* p) {
    uint32_t a;
    asm("{ .reg .u64 t; cvta.to.shared.u64 t, %1; cvt.u32.u64 %0, t; }" : "=r"(a) : "l"(p));
    return a;
}
#define CP_ASYNC16(dst, src) \
    asm volatile("cp.async.cg.shared.global [%0], [%1], 16;" :: "r"(dst), "l"(src) : "memory")
#define CP_COMMIT() asm volatile("cp.async.commit_group;" ::: "memory")
#define CP_WAIT1()  asm volatile("cp.async.wait_group 1;" ::: "memory")

#define LDMATRIX_X4(r0, r1, r2, r3, addr) \
    asm volatile("ldmatrix.sync.aligned.m8n8.x4.shared.b16 {%0,%1,%2,%3}, [%4];" \
                 : "=r"(r0), "=r"(r1), "=r"(r2), "=r"(r3) : "r"(addr))

#define MMA_BF16(c, a, b0, b1) \
    asm volatile("mma.sync.aligned.m16n8k16.row.col.f32.bf16.bf16.f32 " \
                 "{%0,%1,%2,%3}, {%4,%5,%6,%7}, {%8,%9}, {%0,%1,%2,%3};" \
                 : "+f"((c)[0]), "+f"((c)[1]), "+f"((c)[2]), "+f"((c)[3]) \
                 : "r"((a)[0]), "r"((a)[1]), "r"((a)[2]), "r"((a)[3]), "r"(b0), "r"(b1))

// ================== bias table =============================================
__device__ __forceinline__ int bucket_of(int rp) {
    int b = (rp > 0) ? 16 : 0;
    int a = rp < 0 ? -rp : rp;
    if (a < 8) return b + a;
    double v = 7.0 + (log((double)a / 7.0) / log(128.0 / 7.0)) * 8.0;
    int large = (int)v;
    if (large > 15) large = 15;
    return b + large;
}
__global__ void bias_kernel(const float* __restrict__ rel_emb, float* __restrict__ btab) {
    int idx = blockIdx.x * blockDim.x + threadIdx.x;
    if (idx >= NH_ * NBIAS) return;
    int h = idx / NBIAS;
    int x = idx % NBIAS;
    btab[idx] = rel_emb[bucket_of(x - (T_ - 1)) * NH_ + h];
}

// ================== fp32 -> 3-segment split-bf16 ===========================
// MODE 0 (activations): segments [hi | hi | lo]
// MODE 1 (weights):     segments [hi | lo | hi]
// Pairing per k:  s0: a_hi*w_hi, s1: a_hi*w_lo, s2: a_lo*w_hi (drop lo*lo ~2^-17)
template <int MODE>
__global__ void split3_kernel(const float* __restrict__ in, __nv_bfloat16* __restrict__ out,
                              int nrows) {
    int i = blockIdx.x * blockDim.x + threadIdx.x;
    if (i >= nrows * (D_ / 4)) return;
    int r = i / (D_ / 4);
    int c = (i % (D_ / 4)) * 4;
    float4 v = *(const float4*)(in + (size_t)r * D_ + c);
    __nv_bfloat16 h0 = __float2bfloat16_rn(v.x);
    __nv_bfloat16 h1 = __float2bfloat16_rn(v.y);
    __nv_bfloat16 h2 = __float2bfloat16_rn(v.z);
    __nv_bfloat16 h3 = __float2bfloat16_rn(v.w);
    __nv_bfloat16 l0 = __float2bfloat16_rn(v.x - __bfloat162float(h0));
    __nv_bfloat16 l1 = __float2bfloat16_rn(v.y - __bfloat162float(h1));
    __nv_bfloat16 l2 = __float2bfloat16_rn(v.z - __bfloat162float(h2));
    __nv_bfloat16 l3 = __float2bfloat16_rn(v.w - __bfloat162float(h3));
    __nv_bfloat162 hv0 = __halves2bfloat162(h0, h1);
    __nv_bfloat162 hv1 = __halves2bfloat162(h2, h3);
    __nv_bfloat162 lv0 = __halves2bfloat162(l0, l1);
    __nv_bfloat162 lv1 = __halves2bfloat162(l2, l3);
    __nv_bfloat16* base = out + (size_t)r * K3_ + c;
    ((__nv_bfloat162*)(base))[0] = hv0;                       // seg 0: hi
    ((__nv_bfloat162*)(base))[1] = hv1;
    if (MODE == 0) {
        ((__nv_bfloat162*)(base + D_))[0]     = hv0;          // seg 1: hi
        ((__nv_bfloat162*)(base + D_))[1]     = hv1;
        ((__nv_bfloat162*)(base + 2 * D_))[0] = lv0;          // seg 2: lo
        ((__nv_bfloat162*)(base + 2 * D_))[1] = lv1;
    } else {
        ((__nv_bfloat162*)(base + D_))[0]     = lv0;          // seg 1: lo
        ((__nv_bfloat162*)(base + D_))[1]     = lv1;
        ((__nv_bfloat162*)(base + 2 * D_))[0] = hv0;          // seg 2: hi
        ((__nv_bfloat162*)(base + 2 * D_))[1] = hv1;
    }
}

// ================== HMMA bf16 GEMM =========================================
// out[m,n] = sum_k A3[m,k] * W3[n,k]   (M=8192, N=1024, K=3072, bf16 -> fp32)
// CTA 128x128x32, 256 thr (8 warps, warp tile 64x32), 3-stage cp.async pipe.
// SMEM tiles: [128 rows][32 bf16 = 64B], 16B units swizzled: u ^= (row>>1)&3.
#define BK_ 32
#define GSTAGES 3
#define TILE_BYTES (128 * 64)                 // 8KB per operand tile
#define STAGE_BYTES (2 * TILE_BYTES)          // 16KB
#define GITERS (K3_ / BK_)                    // 96

__global__ __launch_bounds__(256, 1)
void gemm_hmma(const __nv_bfloat16* __restrict__ A, const __nv_bfloat16* __restrict__ W,
               float* __restrict__ out) {
    __shared__ __align__(128) char smem[GSTAGES * STAGE_BYTES];   // 48KB static

    const int tid  = threadIdx.x;
    const int wid  = tid >> 5;
    const int lane = tid & 31;
    const int wm   = wid & 1;          // warp m: 0..1 (64 rows each)
    const int wn   = wid >> 1;         // warp n: 0..3 (32 cols each)
    const int m0   = blockIdx.y * 128;
    const int n0   = blockIdx.x * 128;
    const uint32_t sb = smem_u32(smem);

    float acc[4][4][4];
#pragma unroll
    for (int i = 0; i < 4; i++)
#pragma unroll
        for (int j = 0; j < 4; j++)
#pragma unroll
            for (int q = 0; q < 4; q++) acc[i][j][q] = 0.f;

    // ---- stage loader: iter it -> stage it%3 ----
    auto load_stage = [&](int it) {
        const uint32_t st = sb + (uint32_t)(it % GSTAGES) * STAGE_BYTES;
        const int kb = it * BK_;
#pragma unroll
        for (int j = 0; j < 2; j++) {          // A: 512 16B units / 256 thr
            int idx = tid * 2 + j;
            int row = idx >> 2, u = idx & 3;
            uint32_t dst = st + row * 64 + ((u ^ ((row >> 1) & 3)) << 4);
            const void* src = A + (size_t)(m0 + row) * K3_ + kb + u * 8;
            CP_ASYNC16(dst, src);
        }
#pragma unroll
        for (int j = 0; j < 2; j++) {          // B
            int idx = tid * 2 + j;
            int row = idx >> 2, u = idx & 3;
            uint32_t dst = st + TILE_BYTES + row * 64 + ((u ^ ((row >> 1) & 3)) << 4);
            const void* src = W + (size_t)(n0 + row) * K3_ + kb + u * 8;
            CP_ASYNC16(dst, src);
        }
        CP_COMMIT();
    };

    load_stage(0);
    load_stage(1);

    for (int it = 0; it < GITERS; it++) {
        CP_WAIT1();                  // stage it complete
        __syncthreads();
        if (it + 2 < GITERS) load_stage(it + 2);
        else CP_COMMIT();            // keep group accounting exact

        const uint32_t aB = sb + (uint32_t)(it % GSTAGES) * STAGE_BYTES;
        const uint32_t bB = aB + TILE_BYTES;

#pragma unroll
        for (int ks = 0; ks < 2; ks++) {       // two k16 panels per BK=32
            uint32_t a[4][4];
#pragma unroll
            for (int fm = 0; fm < 4; fm++) {
                int row = wm * 64 + fm * 16 + (lane & 15);
                int u = ks * 2 + (lane >> 4);
                uint32_t ad = aB + row * 64 + ((u ^ ((row >> 1) & 3)) << 4);
                LDMATRIX_X4(a[fm][0], a[fm][1], a[fm][2], a[fm][3], ad);
            }
            uint32_t b[2][4];
#pragma unroll
            for (int fp = 0; fp < 2; fp++) {
                int n = wn * 32 + fp * 16 + (lane & 7) + ((lane >> 4) << 3);
                int u = ks * 2 + ((lane >> 3) & 1);
                uint32_t bd = bB + n * 64 + ((u ^ ((n >> 1) & 3)) << 4);
                LDMATRIX_X4(b[fp][0], b[fp][1], b[fp][2], b[fp][3], bd);
            }
#pragma unroll
            for (int fm = 0; fm < 4; fm++)
#pragma unroll
                for (int fp = 0; fp < 2; fp++) {
                    MMA_BF16(acc[fm][fp * 2 + 0], a[fm], b[fp][0], b[fp][1]);
                    MMA_BF16(acc[fm][fp * 2 + 1], a[fm], b[fp][2], b[fp][3]);
                }
        }
        __syncthreads();
    }

    // ---- epilogue: c frag (row lane/4 (+8), col 2*(lane%4)+{0,1}) ----
    const int cr = lane >> 2;
    const int cc = 2 * (lane & 3);
#pragma unroll
    for (int fm = 0; fm < 4; fm++) {
        int r = m0 + wm * 64 + fm * 16 + cr;
#pragma unroll
        for (int fn = 0; fn < 4; fn++) {
            int col = n0 + wn * 32 + fn * 8 + cc;
            *(float2*)(out + (size_t)r * D_ + col) =
                make_float2(acc[fm][fn][0], acc[fm][fn][1]);
            *(float2*)(out + (size_t)(r + 8) * D_ + col) =
                make_float2(acc[fm][fn][2], acc[fm][fn][3]);
        }
    }
}

// ================== fused flash attention (fp32, row-major Q/K/V) ==========
__global__ __launch_bounds__(256, 2)
void attn_kernel(const float* __restrict__ Q, const float* __restrict__ K,
                 const float* __restrict__ V, const float* __restrict__ btab,
                 float* __restrict__ out) {
    __shared__ float Qs [64 * 64];
    __shared__ float KPs[64 * 64];
    __shared__ float Vs [64 * 64];

    const int tid = threadIdx.x;
    const int ty = tid >> 4;
    const int tx = tid & 15;
    const int bh = blockIdx.y;
    const int h  = bh & (NH_ - 1);
    const int b  = bh >> 4;
    const int q0 = blockIdx.x * 64;

    const float* Qb = Q + (size_t)b * T_ * D_ + h * HS_;
    const float* Kb = K + (size_t)b * T_ * D_ + h * HS_;
    const float* Vb = V + (size_t)b * T_ * D_ + h * HS_;

#pragma unroll
    for (int s = 0; s < 4; s++) {
        int f = tid + s * 256;
        int r = f & 63, dg = f >> 6;
        float4 v = *(const float4*)(Qb + (size_t)(q0 + r) * D_ + 4 * dg);
        Qs[(4 * dg + 0) * 64 + r] = v.x * 0.125f;
        Qs[(4 * dg + 1) * 64 + r] = v.y * 0.125f;
        Qs[(4 * dg + 2) * 64 + r] = v.z * 0.125f;
        Qs[(4 * dg + 3) * 64 + r] = v.w * 0.125f;
    }

    float o[4][4];
    float m_r[4], l_r[4];
#pragma unroll
    for (int i = 0; i < 4; i++) {
        m_r[i] = -1e30f; l_r[i] = 0.f;
#pragma unroll
        for (int j = 0; j < 4; j++) o[i][j] = 0.f;
    }

    for (int k0 = 0; k0 < T_; k0 += 64) {
        __syncthreads();
#pragma unroll
        for (int s = 0; s < 4; s++) {
            int f = tid + s * 256;
            int r = f & 63, dg = f >> 6;
            float4 v = *(const float4*)(Kb + (size_t)(k0 + r) * D_ + 4 * dg);
            KPs[(4 * dg + 0) * 64 + r] = v.x;
            KPs[(4 * dg + 1) * 64 + r] = v.y;
            KPs[(4 * dg + 2) * 64 + r] = v.z;
            KPs[(4 * dg + 3) * 64 + r] = v.w;
        }
#pragma unroll
        for (int s = 0; s < 4; s++) {
            int f = tid + s * 256;
            int kk = f >> 4, cg = f & 15;
            *(float4*)(Vs + kk * 64 + 4 * cg) =
                *(const float4*)(Vb + (size_t)(k0 + kk) * D_ + 4 * cg);
        }
        __syncthreads();

        float s_[4][4];
#pragma unroll
        for (int i = 0; i < 4; i++)
#pragma unroll
            for (int j = 0; j < 4; j++) s_[i][j] = 0.f;
#pragma unroll 16
        for (int d = 0; d < 64; d++) {
            float4 a  = *(const float4*)(Qs  + d * 64 + 4 * ty);
            float4 bb = *(const float4*)(KPs + d * 64 + 4 * tx);
            s_[0][0] += a.x * bb.x; s_[0][1] += a.x * bb.y; s_[0][2] += a.x * bb.z; s_[0][3] += a.x * bb.w;
            s_[1][0] += a.y * bb.x; s_[1][1] += a.y * bb.y; s_[1][2] += a.y * bb.z; s_[1][3] += a.y * bb.w;
            s_[2][0] += a.z * bb.x; s_[2][1] += a.z * bb.y; s_[2][2] += a.z * bb.z; s_[2][3] += a.z * bb.w;
            s_[3][0] += a.w * bb.x; s_[3][1] += a.w * bb.y; s_[3][2] += a.w * bb.z; s_[3][3] += a.w * bb.w;
        }

        const float* bp = btab + h * NBIAS + (T_ - 1) + (k0 + 4 * tx) - (q0 + 4 * ty);
#pragma unroll
        for (int i = 0; i < 4; i++)
#pragma unroll
            for (int j = 0; j < 4; j++) s_[i][j] += bp[j - i];

        float mt[4];
#pragma unroll
        for (int i = 0; i < 4; i++)
            mt[i] = fmaxf(fmaxf(s_[i][0], s_[i][1]), fmaxf(s_[i][2], s_[i][3]));
#pragma unroll
        for (int off = 8; off; off >>= 1)
#pragma unroll
            for (int i = 0; i < 4; i++)
                mt[i] = fmaxf(mt[i], __shfl_xor_sync(0xffffffffu, mt[i], off));

        float alpha[4];
#pragma unroll
        for (int i = 0; i < 4; i++) {
            float mn = fmaxf(m_r[i], mt[i]);
            alpha[i] = __expf(m_r[i] - mn);
            m_r[i] = mn;
        }
        float ls[4];
#pragma unroll
        for (int i = 0; i < 4; i++) {
            ls[i] = 0.f;
#pragma unroll
            for (int j = 0; j < 4; j++) {
                float p = __expf(s_[i][j] - m_r[i]);
                s_[i][j] = p;
                ls[i] += p;
            }
        }
#pragma unroll
        for (int off = 8; off; off >>= 1)
#pragma unroll
            for (int i = 0; i < 4; i++)
                ls[i] += __shfl_xor_sync(0xffffffffu, ls[i], off);
#pragma unroll
        for (int i = 0; i < 4; i++) {
            l_r[i] = l_r[i] * alpha[i] + ls[i];
#pragma unroll
            for (int j = 0; j < 4; j++) o[i][j] *= alpha[i];
        }

        __syncthreads();
#pragma unroll
        for (int j = 0; j < 4; j++) {
            float4 v = make_float4(s_[0][j], s_[1][j], s_[2][j], s_[3][j]);
            *(float4*)(KPs + (4 * tx + j) * 64 + ((ty ^ tx) << 2)) = v;
        }
        __syncthreads();

#pragma unroll 16
        for (int kk = 0; kk < 64; kk++) {
            int g = (kk >> 2) & 15;
            float4 a  = *(const float4*)(KPs + kk * 64 + ((ty ^ g) << 2));
            float4 bb = *(const float4*)(Vs + kk * 64 + 4 * tx);
            o[0][0] += a.x * bb.x; o[0][1] += a.x * bb.y; o[0][2] += a.x * bb.z; o[0][3] += a.x * bb.w;
            o[1][0] += a.y * bb.x; o[1][1] += a.y * bb.y; o[1][2] += a.y * bb.z; o[1][3] += a.y * bb.w;
            o[2][0] += a.z * bb.x; o[2][1] += a.z * bb.y; o[2][2] += a.z * bb.z; o[2][3] += a.z * bb.w;
            o[3][0] += a.w * bb.x; o[3][1] += a.w * bb.y; o[3][2] += a.w * bb.z; o[3][3] += a.w * bb.w;
        }
    }

#pragma unroll
    for (int i = 0; i < 4; i++) {
        float inv = 1.0f / l_r[i];
        int t = q0 + 4 * ty + i;
        float4 v = make_float4(o[i][0] * inv, o[i][1] * inv, o[i][2] * inv, o[i][3] * inv);
        *(float4*)(out + (size_t)(b * T_ + t) * D_ + h * HS_ + 4 * tx) = v;
    }
}

// ================== launch ==================================================
extern "C" void kernel_launch(void* const* d_in, const int* in_sizes, int n_in,
                              void* d_out, int out_size) {
    const float* queries = (const float*)d_in[0];
    const float* Wq      = (const float*)d_in[1];
    const float* Wk      = (const float*)d_in[2];
    const float* Wv      = (const float*)d_in[3];
    const float* Wo      = (const float*)d_in[4];
    const float* rel_emb = (const float*)d_in[5];
    float* out = (float*)d_out;

    __nv_bfloat16 *gA3, *gAO3, *gW3;
    float *gQ, *gK, *gV, *gAO, *gB;
    cudaGetSymbolAddress((void**)&gA3,  g_A3);
    cudaGetSymbolAddress((void**)&gAO3, g_AO3);
    cudaGetSymbolAddress((void**)&gW3,  g_W3);
    cudaGetSymbolAddress((void**)&gQ,   g_Q);
    cudaGetSymbolAddress((void**)&gK,   g_K);
    cudaGetSymbolAddress((void**)&gV,   g_V);
    cudaGetSymbolAddress((void**)&gAO,  g_AO);
    cudaGetSymbolAddress((void**)&gB,   g_bias);

    const size_t WOFF = (size_t)D_ * K3_;

    // 1) bias table + operand splits
    bias_kernel<<<(NH_ * NBIAS + 255) / 256, 256>>>(rel_emb, gB);
    split3_kernel<0><<<(M_ * (D_ / 4) + 255) / 256, 256>>>(queries, gA3, M_);
    split3_kernel<1><<<(D_ * (D_ / 4) + 255) / 256, 256>>>(Wq, gW3 + 0 * WOFF, D_);
    split3_kernel<1><<<(D_ * (D_ / 4) + 255) / 256, 256>>>(Wk, gW3 + 1 * WOFF, D_);
    split3_kernel<1><<<(D_ * (D_ / 4) + 255) / 256, 256>>>(Wv, gW3 + 2 * WOFF, D_);
    split3_kernel<1><<<(D_ * (D_ / 4) + 255) / 256, 256>>>(Wo, gW3 + 3 * WOFF, D_);

    // 2) Q/K/V projections on tensor cores (HMMA, row-major outputs)
    dim3 gGrid(D_ / 128, M_ / 128);    // (8, 64)
    gemm_hmma<<<gGrid, 256>>>(gA3, gW3 + 0 * WOFF, gQ);
    gemm_hmma<<<gGrid, 256>>>(gA3, gW3 + 1 * WOFF, gK);
    gemm_hmma<<<gGrid, 256>>>(gA3, gW3 + 2 * WOFF, gV);

    // 3) fused attention (fp32)
    dim3 aGrid(T_ / 64, B_ * NH_);     // (32, 64)
    attn_kernel<<<aGrid, 256>>>(gQ, gK, gV, gB, gAO);

    // 4) output projection
    split3_kernel<0><<<(M_ * (D_ / 4) + 255) / 256, 256>>>(gAO, gAO3, M_);
    gemm_hmma<<<gGrid, 256>>>(gAO3, gW3 + 3 * WOFF, out);
}

// round 4
// speedup vs baseline: 2.4801x; 1.9278x over previous
#include <cuda_runtime.h>
#include <cuda_bf16.h>
#include <math.h>
#include <stdint.h>

#define B_  4
#define T_  2048
#define D_  1024
#define NH_ 16
#define HS_ 64
#define NBIAS (2*T_ - 1)   // 4095
#define M_  (B_*T_)        // 8192
#define K3_ 3072           // split-bf16 K: [hi | hi | lo] x [hi | lo | hi]

// ---------------- scratch (device globals: no allocation allowed) ----------
__device__ __nv_bfloat16 g_A3 [M_*(size_t)K3_];
__device__ __nv_bfloat16 g_AO3[M_*(size_t)K3_];
__device__ __nv_bfloat16 g_W3 [4*(size_t)D_*K3_];
__device__ float g_Q [M_*(size_t)D_];              // row-major [b*t, d]
__device__ float g_K [M_*(size_t)D_];
__device__ float g_V [M_*(size_t)D_];
__device__ float g_AO[M_*(size_t)D_];
__device__ float g_bias[NH_*NBIAS];

// ============================ PTX helpers ==================================
__device__ __forceinline__ uint32_t smem_u32(const void* p) {
    uint32_t a;
    asm("{ .reg .u64 t; cvta.to.shared.u64 t, %1; cvt.u32.u64 %0, t; }" : "=r"(a) : "l"(p));
    return a;
}
#define CP_ASYNC16(dst, src) \
    asm volatile("cp.async.cg.shared.global [%0], [%1], 16;" :: "r"(dst), "l"(src) : "memory")
#define CP_COMMIT() asm volatile("cp.async.commit_group;" ::: "memory")
#define CP_WAIT1()  asm volatile("cp.async.wait_group 1;" ::: "memory")

#define LDMATRIX_X4(r0, r1, r2, r3, addr) \
    asm volatile("ldmatrix.sync.aligned.m8n8.x4.shared.b16 {%0,%1,%2,%3}, [%4];" \
                 : "=r"(r0), "=r"(r1), "=r"(r2), "=r"(r3) : "r"(addr))
#define LDMATRIX_X4_T(r0, r1, r2, r3, addr) \
    asm volatile("ldmatrix.sync.aligned.m8n8.x4.trans.shared.b16 {%0,%1,%2,%3}, [%4];" \
                 : "=r"(r0), "=r"(r1), "=r"(r2), "=r"(r3) : "r"(addr))

#define MMA_BF16(c, a, b0, b1) \
    asm volatile("mma.sync.aligned.m16n8k16.row.col.f32.bf16.bf16.f32 " \
                 "{%0,%1,%2,%3}, {%4,%5,%6,%7}, {%8,%9}, {%0,%1,%2,%3};" \
                 : "+f"((c)[0]), "+f"((c)[1]), "+f"((c)[2]), "+f"((c)[3]) \
                 : "r"((a)[0]), "r"((a)[1]), "r"((a)[2]), "r"((a)[3]), "r"(b0), "r"(b1))

// split a pair of floats into packed bf16x2 hi + lo ({x=low lane})
__device__ __forceinline__ void split2(float a, float b, uint32_t& hi, uint32_t& lo) {
    __nv_bfloat16 ha = __float2bfloat16_rn(a), hb = __float2bfloat16_rn(b);
    float la = a - __bfloat162float(ha), lb = b - __bfloat162float(hb);
    __nv_bfloat162 hv = __halves2bfloat162(ha, hb);
    __nv_bfloat162 lv = __halves2bfloat162(__float2bfloat16_rn(la), __float2bfloat16_rn(lb));
    hi = *(uint32_t*)&hv;
    lo = *(uint32_t*)&lv;
}

// ================== bias table =============================================
__device__ __forceinline__ int bucket_of(int rp) {
    int b = (rp > 0) ? 16 : 0;
    int a = rp < 0 ? -rp : rp;
    if (a < 8) return b + a;
    double v = 7.0 + (log((double)a / 7.0) / log(128.0 / 7.0)) * 8.0;
    int large = (int)v;
    if (large > 15) large = 15;
    return b + large;
}
__global__ void bias_kernel(const float* __restrict__ rel_emb, float* __restrict__ btab) {
    int idx = blockIdx.x * blockDim.x + threadIdx.x;
    if (idx >= NH_ * NBIAS) return;
    int h = idx / NBIAS;
    int x = idx % NBIAS;
    btab[idx] = rel_emb[bucket_of(x - (T_ - 1)) * NH_ + h];
}

// ================== fp32 -> 3-segment split-bf16 ===========================
template <int MODE>
__global__ void split3_kernel(const float* __restrict__ in, __nv_bfloat16* __restrict__ out,
                              int nrows) {
    int i = blockIdx.x * blockDim.x + threadIdx.x;
    if (i >= nrows * (D_ / 4)) return;
    int r = i / (D_ / 4);
    int c = (i % (D_ / 4)) * 4;
    float4 v = *(const float4*)(in + (size_t)r * D_ + c);
    uint32_t h0, l0, h1, l1;
    split2(v.x, v.y, h0, l0);
    split2(v.z, v.w, h1, l1);
    uint32_t* base = (uint32_t*)(out + (size_t)r * K3_ + c);
    base[0] = h0; base[1] = h1;                               // seg 0: hi
    uint32_t* s1 = (uint32_t*)(out + (size_t)r * K3_ + D_ + c);
    uint32_t* s2 = (uint32_t*)(out + (size_t)r * K3_ + 2 * D_ + c);
    if (MODE == 0) { s1[0] = h0; s1[1] = h1; s2[0] = l0; s2[1] = l1; }  // [hi|hi|lo]
    else           { s1[0] = l0; s1[1] = l1; s2[0] = h0; s2[1] = h1; }  // [hi|lo|hi]
}

// ================== HMMA bf16 GEMM (projections) ===========================
#define BK_ 32
#define GSTAGES 3
#define TILE_BYTES (128 * 64)
#define STAGE_BYTES (2 * TILE_BYTES)
#define GITERS (K3_ / BK_)

__global__ __launch_bounds__(256, 1)
void gemm_hmma(const __nv_bfloat16* __restrict__ A, const __nv_bfloat16* __restrict__ W,
               float* __restrict__ out) {
    __shared__ __align__(128) char smem[GSTAGES * STAGE_BYTES];

    const int tid  = threadIdx.x;
    const int wid  = tid >> 5;
    const int lane = tid & 31;
    const int wm   = wid & 1;
    const int wn   = wid >> 1;
    const int m0   = blockIdx.y * 128;
    const int n0   = blockIdx.x * 128;
    const uint32_t sb = smem_u32(smem);

    float acc[4][4][4];
#pragma unroll
    for (int i = 0; i < 4; i++)
#pragma unroll
        for (int j = 0; j < 4; j++)
#pragma unroll
            for (int q = 0; q < 4; q++) acc[i][j][q] = 0.f;

    auto load_stage = [&](int it) {
        const uint32_t st = sb + (uint32_t)(it % GSTAGES) * STAGE_BYTES;
        const int kb = it * BK_;
#pragma unroll
        for (int j = 0; j < 2; j++) {
            int idx = tid * 2 + j;
            int row = idx >> 2, u = idx & 3;
            uint32_t dst = st + row * 64 + ((u ^ ((row >> 1) & 3)) << 4);
            const void* src = A + (size_t)(m0 + row) * K3_ + kb + u * 8;
            CP_ASYNC16(dst, src);
        }
#pragma unroll
        for (int j = 0; j < 2; j++) {
            int idx = tid * 2 + j;
            int row = idx >> 2, u = idx & 3;
            uint32_t dst = st + TILE_BYTES + row * 64 + ((u ^ ((row >> 1) & 3)) << 4);
            const void* src = W + (size_t)(n0 + row) * K3_ + kb + u * 8;
            CP_ASYNC16(dst, src);
        }
        CP_COMMIT();
    };

    load_stage(0);
    load_stage(1);

    for (int it = 0; it < GITERS; it++) {
        CP_WAIT1();
        __syncthreads();
        if (it + 2 < GITERS) load_stage(it + 2);
        else CP_COMMIT();

        const uint32_t aB = sb + (uint32_t)(it % GSTAGES) * STAGE_BYTES;
        const uint32_t bB = aB + TILE_BYTES;

#pragma unroll
        for (int ks = 0; ks < 2; ks++) {
            uint32_t a[4][4];
#pragma unroll
            for (int fm = 0; fm < 4; fm++) {
                int row = wm * 64 + fm * 16 + (lane & 15);
                int u = ks * 2 + (lane >> 4);
                uint32_t ad = aB + row * 64 + ((u ^ ((row >> 1) & 3)) << 4);
                LDMATRIX_X4(a[fm][0], a[fm][1], a[fm][2], a[fm][3], ad);
            }
            uint32_t b[2][4];
#pragma unroll
            for (int fp = 0; fp < 2; fp++) {
                int n = wn * 32 + fp * 16 + (lane & 7) + ((lane >> 4) << 3);
                int u = ks * 2 + ((lane >> 3) & 1);
                uint32_t bd = bB + n * 64 + ((u ^ ((n >> 1) & 3)) << 4);
                LDMATRIX_X4(b[fp][0], b[fp][1], b[fp][2], b[fp][3], bd);
            }
#pragma unroll
            for (int fm = 0; fm < 4; fm++)
#pragma unroll
                for (int fp = 0; fp < 2; fp++) {
                    MMA_BF16(acc[fm][fp * 2 + 0], a[fm], b[fp][0], b[fp][1]);
                    MMA_BF16(acc[fm][fp * 2 + 1], a[fm], b[fp][2], b[fp][3]);
                }
        }
        __syncthreads();
    }

    const int cr = lane >> 2;
    const int cc = 2 * (lane & 3);
#pragma unroll
    for (int fm = 0; fm < 4; fm++) {
        int r = m0 + wm * 64 + fm * 16 + cr;
#pragma unroll
        for (int fn = 0; fn < 4; fn++) {
            int col = n0 + wn * 32 + fn * 8 + cc;
            *(float2*)(out + (size_t)r * D_ + col) =
                make_float2(acc[fm][fn][0], acc[fm][fn][1]);
            *(float2*)(out + (size_t)(r + 8) * D_ + col) =
                make_float2(acc[fm][fn][2], acc[fm][fn][3]);
        }
    }
}

// ================== HMMA flash attention ===================================
// CTA: 128 q-rows of one (b,h). 8 warps, 16 q-rows each. k-tiles of 64.
// SMEM (dyn 64KB): Q3 [128 rows][256B: q_hi(64c)|q_lo(64c)]  @ 0
//                  K3 [ 64 rows][256B: k_hi|k_lo]            @ 32768
//                  V3 [128 rows][128B]: rows 0-63 v_hi, 64-127 v_lo @ 49152
// Swizzle (256B rows): unit u(0..15): u' = (u&8) | ((u^row)&7)
// Swizzle (128B rows): u' = u ^ (row&7)
#define QT 128
#define KT 64
#define ASM_Q 0u
#define ASM_K 32768u
#define ASM_V 49152u
#define ATTN_SMEM 65536

__global__ __launch_bounds__(256, 2)
void attn_hmma(const float* __restrict__ Q, const float* __restrict__ K,
               const float* __restrict__ V, const float* __restrict__ btab,
               float* __restrict__ out) {
    extern __shared__ char sm[];
    const uint32_t sb = smem_u32(sm);

    const int tid  = threadIdx.x;
    const int w    = tid >> 5;
    const int lane = tid & 31;
    const int bh = blockIdx.y;
    const int h  = bh & (NH_ - 1);
    const int b  = bh >> 4;
    const int q0 = blockIdx.x * QT;

    const float* Qb = Q + (size_t)b * T_ * D_ + h * HS_;
    const float* Kb = K + (size_t)b * T_ * D_ + h * HS_;
    const float* Vb = V + (size_t)b * T_ * D_ + h * HS_;
    const float* bias_h = btab + h * NBIAS + (T_ - 1);

    // ---- load Q tile once: split into hi|lo, pre-scaled by 1/8 ----
#pragma unroll
    for (int i = tid; i < QT * 16; i += 256) {
        int row = i >> 4, g = i & 15;                 // g: float4 group (cols 4g..4g+3)
        float4 v = *(const float4*)(Qb + (size_t)(q0 + row) * D_ + 4 * g);
        uint32_t h0, l0, h1, l1;
        split2(v.x * 0.125f, v.y * 0.125f, h0, l0);
        split2(v.z * 0.125f, v.w * 0.125f, h1, l1);
        char* rp = sm + ASM_Q + row * 256;
        int u0 = g >> 1;                              // hi bytes 8g, 8g+4
        int su0 = (u0 ^ row) & 7;
        *(uint32_t*)(rp + su0 * 16 + ((8 * g) & 15))     = h0;
        *(uint32_t*)(rp + su0 * 16 + ((8 * g + 4) & 15)) = h1;
        int u1 = 8 + (g >> 1);                        // lo bytes 128+8g
        int su1 = 8 | ((u1 ^ row) & 7);
        *(uint32_t*)(rp + su1 * 16 + ((8 * g) & 15))     = l0;
        *(uint32_t*)(rp + su1 * 16 + ((8 * g + 4) & 15)) = l1;
    }

    float ofr[8][4];
    float mrow[2] = {-1e30f, -1e30f};
    float lrow[2] = {0.f, 0.f};
#pragma unroll
    for (int j = 0; j < 8; j++)
#pragma unroll
        for (int q = 0; q < 4; q++) ofr[j][q] = 0.f;

    for (int k0 = 0; k0 < T_; k0 += KT) {
        __syncthreads();
        // ---- K tile: split hi|lo ----
#pragma unroll
        for (int i = tid; i < KT * 16; i += 256) {
            int row = i >> 4, g = i & 15;
            float4 v = *(const float4*)(Kb + (size_t)(k0 + row) * D_ + 4 * g);
            uint32_t h0, l0, h1, l1;
            split2(v.x, v.y, h0, l0);
            split2(v.z, v.w, h1, l1);
            char* rp = sm + ASM_K + row * 256;
            int su0 = ((g >> 1) ^ row) & 7;
            *(uint32_t*)(rp + su0 * 16 + ((8 * g) & 15))     = h0;
            *(uint32_t*)(rp + su0 * 16 + ((8 * g + 4) & 15)) = h1;
            int su1 = 8 | (((8 + (g >> 1)) ^ row) & 7);
            *(uint32_t*)(rp + su1 * 16 + ((8 * g) & 15))     = l0;
            *(uint32_t*)(rp + su1 * 16 + ((8 * g + 4) & 15)) = l1;
        }
        // ---- V tile: rows 0-63 hi, 64-127 lo ([key][hs] layout) ----
#pragma unroll
        for (int i = tid; i < KT * 16; i += 256) {
            int key = i >> 4, g = i & 15;
            float4 v = *(const float4*)(Vb + (size_t)(k0 + key) * D_ + 4 * g);
            uint32_t h0, l0, h1, l1;
            split2(v.x, v.y, h0, l0);
            split2(v.z, v.w, h1, l1);
            int u = g >> 1;
            char* rh = sm + ASM_V + key * 128;
            int suh = (u ^ (key & 7));
            *(uint32_t*)(rh + suh * 16 + ((8 * g) & 15))     = h0;
            *(uint32_t*)(rh + suh * 16 + ((8 * g + 4) & 15)) = h1;
            char* rl = sm + ASM_V + (64 + key) * 128;
            *(uint32_t*)(rl + suh * 16 + ((8 * g) & 15))     = l0;   // (key+64)&7 == key&7
            *(uint32_t*)(rl + suh * 16 + ((8 * g + 4) & 15)) = l1;
        }
        __syncthreads();

        // ---- S = (Q/8) K^T via 3-term split ----
        float sf[8][4];
#pragma unroll
        for (int j = 0; j < 8; j++)
#pragma unroll
            for (int q = 0; q < 4; q++) sf[j][q] = 0.f;

#pragma unroll
        for (int u = 0; u < 4; u++) {
            uint32_t ah[4], al[4];
            {
                int row = w * 16 + (lane & 15);
                int uh = 2 * u + (lane >> 4);
                uint32_t adh = sb + ASM_Q + row * 256 + (((uh ^ row) & 7) << 4);
                LDMATRIX_X4(ah[0], ah[1], ah[2], ah[3], adh);
                int ul = 8 + 2 * u + (lane >> 4);
                uint32_t adl = sb + ASM_Q + row * 256 + ((8 | ((ul ^ row) & 7)) << 4);
                LDMATRIX_X4(al[0], al[1], al[2], al[3], adl);
            }
#pragma unroll
            for (int fp = 0; fp < 4; fp++) {
                int n = fp * 16 + (lane & 7) + ((lane >> 4) << 3);
                int uh = 2 * u + ((lane >> 3) & 1);
                uint32_t bh_[4], bl_[4];
                uint32_t bdh = sb + ASM_K + n * 256 + (((uh ^ n) & 7) << 4);
                LDMATRIX_X4(bh_[0], bh_[1], bh_[2], bh_[3], bdh);
                int ul = 8 + 2 * u + ((lane >> 3) & 1);
                uint32_t bdl = sb + ASM_K + n * 256 + ((8 | ((ul ^ n) & 7)) << 4);
                LDMATRIX_X4(bl_[0], bl_[1], bl_[2], bl_[3], bdl);
                MMA_BF16(sf[2 * fp + 0], ah, bh_[0], bh_[1]);   // q_hi * k_hi
                MMA_BF16(sf[2 * fp + 1], ah, bh_[2], bh_[3]);
                MMA_BF16(sf[2 * fp + 0], ah, bl_[0], bl_[1]);   // q_hi * k_lo
                MMA_BF16(sf[2 * fp + 1], ah, bl_[2], bl_[3]);
                MMA_BF16(sf[2 * fp + 0], al, bh_[0], bh_[1]);   // q_lo * k_hi
                MMA_BF16(sf[2 * fp + 1], al, bh_[2], bh_[3]);
            }
        }

        // ---- + bias ----
        const int r0g = q0 + w * 16 + (lane >> 2);
#pragma unroll
        for (int j = 0; j < 8; j++) {
            int dk = k0 + 8 * j + 2 * (lane & 3) - r0g;
            sf[j][0] += bias_h[dk];
            sf[j][1] += bias_h[dk + 1];
            sf[j][2] += bias_h[dk - 8];
            sf[j][3] += bias_h[dk - 7];
        }

        // ---- online softmax (rows r0=lane/4, r1=r0+8 of warp's 16) ----
        float mt0 = -1e30f, mt1 = -1e30f;
#pragma unroll
        for (int j = 0; j < 8; j++) {
            mt0 = fmaxf(mt0, fmaxf(sf[j][0], sf[j][1]));
            mt1 = fmaxf(mt1, fmaxf(sf[j][2], sf[j][3]));
        }
        mt0 = fmaxf(mt0, __shfl_xor_sync(0xffffffffu, mt0, 1));
        mt0 = fmaxf(mt0, __shfl_xor_sync(0xffffffffu, mt0, 2));
        mt1 = fmaxf(mt1, __shfl_xor_sync(0xffffffffu, mt1, 1));
        mt1 = fmaxf(mt1, __shfl_xor_sync(0xffffffffu, mt1, 2));

        float mn0 = fmaxf(mrow[0], mt0), mn1 = fmaxf(mrow[1], mt1);
        float alpha0 = __expf(mrow[0] - mn0), alpha1 = __expf(mrow[1] - mn1);
        mrow[0] = mn0; mrow[1] = mn1;

        float ls0 = 0.f, ls1 = 0.f;
#pragma unroll
        for (int j = 0; j < 8; j++) {
            sf[j][0] = __expf(sf[j][0] - mn0);
            sf[j][1] = __expf(sf[j][1] - mn0);
            sf[j][2] = __expf(sf[j][2] - mn1);
            sf[j][3] = __expf(sf[j][3] - mn1);
            ls0 += sf[j][0] + sf[j][1];
            ls1 += sf[j][2] + sf[j][3];
        }
        ls0 += __shfl_xor_sync(0xffffffffu, ls0, 1);
        ls0 += __shfl_xor_sync(0xffffffffu, ls0, 2);
        ls1 += __shfl_xor_sync(0xffffffffu, ls1, 1);
        ls1 += __shfl_xor_sync(0xffffffffu, ls1, 2);
        lrow[0] = lrow[0] * alpha0 + ls0;
        lrow[1] = lrow[1] * alpha1 + ls1;
#pragma unroll
        for (int j = 0; j < 8; j++) {
            ofr[j][0] *= alpha0; ofr[j][1] *= alpha0;
            ofr[j][2] *= alpha1; ofr[j][3] *= alpha1;
        }

        // ---- O += P * V via 3-term split (p_hi*v_hi + p_hi*v_lo + p_lo*v_hi) ----
#pragma unroll
        for (int kk = 0; kk < 4; kk++) {
            uint32_t ph[4], pl[4];
            split2(sf[2 * kk][0],     sf[2 * kk][1],     ph[0], pl[0]);
            split2(sf[2 * kk][2],     sf[2 * kk][3],     ph[1], pl[1]);
            split2(sf[2 * kk + 1][0], sf[2 * kk + 1][1], ph[2], pl[2]);
            split2(sf[2 * kk + 1][2], sf[2 * kk + 1][3], ph[3], pl[3]);
            const int g = lane >> 3;
            const int rowh = kk * 16 + ((g & 1) << 3) + (lane & 7);
            const int rowl = 64 + rowh;
#pragma unroll
            for (int fb = 0; fb < 4; fb++) {
                int unit = fb * 2 + (g >> 1);
                uint32_t bvh[4], bvl[4];
                uint32_t avh = sb + ASM_V + rowh * 128 + ((unit ^ (rowh & 7)) << 4);
                LDMATRIX_X4_T(bvh[0], bvh[1], bvh[2], bvh[3], avh);
                uint32_t avl = sb + ASM_V + rowl * 128 + ((unit ^ (rowl & 7)) << 4);
                LDMATRIX_X4_T(bvl[0], bvl[1], bvl[2], bvl[3], avl);
                MMA_BF16(ofr[2 * fb + 0], ph, bvh[0], bvh[1]);
                MMA_BF16(ofr[2 * fb + 1], ph, bvh[2], bvh[3]);
                MMA_BF16(ofr[2 * fb + 0], ph, bvl[0], bvl[1]);
                MMA_BF16(ofr[2 * fb + 1], ph, bvl[2], bvl[3]);
                MMA_BF16(ofr[2 * fb + 0], pl, bvh[0], bvh[1]);
                MMA_BF16(ofr[2 * fb + 1], pl, bvh[2], bvh[3]);
            }
        }
    }

    // ---- epilogue ----
    const float inv0 = 1.f / lrow[0], inv1 = 1.f / lrow[1];
    const int r0 = q0 + w * 16 + (lane >> 2), r1 = r0 + 8;
#pragma unroll
    for (int j = 0; j < 8; j++) {
        int col = h * HS_ + 8 * j + 2 * (lane & 3);
        *(float2*)(out + (size_t)(b * T_ + r0) * D_ + col) =
            make_float2(ofr[j][0] * inv0, ofr[j][1] * inv0);
        *(float2*)(out + (size_t)(b * T_ + r1) * D_ + col) =
            make_float2(ofr[j][2] * inv1, ofr[j][3] * inv1);
    }
}

// ================== launch ==================================================
extern "C" void kernel_launch(void* const* d_in, const int* in_sizes, int n_in,
                              void* d_out, int out_size) {
    const float* queries = (const float*)d_in[0];
    const float* Wq      = (const float*)d_in[1];
    const float* Wk      = (const float*)d_in[2];
    const float* Wv      = (const float*)d_in[3];
    const float* Wo      = (const float*)d_in[4];
    const float* rel_emb = (const float*)d_in[5];
    float* out = (float*)d_out;

    __nv_bfloat16 *gA3, *gAO3, *gW3;
    float *gQ, *gK, *gV, *gAO, *gB;
    cudaGetSymbolAddress((void**)&gA3,  g_A3);
    cudaGetSymbolAddress((void**)&gAO3, g_AO3);
    cudaGetSymbolAddress((void**)&gW3,  g_W3);
    cudaGetSymbolAddress((void**)&gQ,   g_Q);
    cudaGetSymbolAddress((void**)&gK,   g_K);
    cudaGetSymbolAddress((void**)&gV,   g_V);
    cudaGetSymbolAddress((void**)&gAO,  g_AO);
    cudaGetSymbolAddress((void**)&gB,   g_bias);

    cudaFuncSetAttribute(attn_hmma, cudaFuncAttributeMaxDynamicSharedMemorySize, ATTN_SMEM);

    const size_t WOFF = (size_t)D_ * K3_;

    bias_kernel<<<(NH_ * NBIAS + 255) / 256, 256>>>(rel_emb, gB);
    split3_kernel<0><<<(M_ * (D_ / 4) + 255) / 256, 256>>>(queries, gA3, M_);
    split3_kernel<1><<<(D_ * (D_ / 4) + 255) / 256, 256>>>(Wq, gW3 + 0 * WOFF, D_);
    split3_kernel<1><<<(D_ * (D_ / 4) + 255) / 256, 256>>>(Wk, gW3 + 1 * WOFF, D_);
    split3_kernel<1><<<(D_ * (D_ / 4) + 255) / 256, 256>>>(Wv, gW3 + 2 * WOFF, D_);
    split3_kernel<1><<<(D_ * (D_ / 4) + 255) / 256, 256>>>(Wo, gW3 + 3 * WOFF, D_);

    dim3 gGrid(D_ / 128, M_ / 128);
    gemm_hmma<<<gGrid, 256>>>(gA3, gW3 + 0 * WOFF, gQ);
    gemm_hmma<<<gGrid, 256>>>(gA3, gW3 + 1 * WOFF, gK);
    gemm_hmma<<<gGrid, 256>>>(gA3, gW3 + 2 * WOFF, gV);

    dim3 aGrid(T_ / QT, B_ * NH_);     // (16, 64)
    attn_hmma<<<aGrid, 256, ATTN_SMEM>>>(gQ, gK, gV, gB, gAO);

    split3_kernel<0><<<(M_ * (D_ / 4) + 255) / 256, 256>>>(gAO, gAO3, M_);
    gemm_hmma<<<gGrid, 256>>>(gAO3, gW3 + 3 * WOFF, out);
}

// round 5
// speedup vs baseline: 2.6340x; 1.0621x over previous
#include <cuda_runtime.h>
#include <cuda_bf16.h>
#include <math.h>
#include <stdint.h>

#define B_  4
#define T_  2048
#define D_  1024
#define NH_ 16
#define HS_ 64
#define NBIAS (2*T_ - 1)   // 4095
#define M_  (B_*T_)        // 8192
#define K3_ 3072           // split-bf16 K: [hi | hi | lo] x [hi | lo | hi]

// ---------------- scratch (device globals: no allocation allowed) ----------
__device__ __nv_bfloat16 g_A3 [M_*(size_t)K3_];
__device__ __nv_bfloat16 g_AO3[M_*(size_t)K3_];
__device__ __nv_bfloat16 g_W3 [4*(size_t)D_*K3_];
__device__ float g_Q [M_*(size_t)D_];              // row-major [b*t, d]
__device__ float g_K [M_*(size_t)D_];
__device__ float g_V [M_*(size_t)D_];
__device__ float g_bias[NH_*NBIAS];

// ============================ PTX helpers ==================================
__device__ __forceinline__ uint32_t smem_u32(const void* p) {
    uint32_t a;
    asm("{ .reg .u64 t; cvta.to.shared.u64 t, %1; cvt.u32.u64 %0, t; }" : "=r"(a) : "l"(p));
    return a;
}
#define CP_ASYNC16(dst, src) \
    asm volatile("cp.async.cg.shared.global [%0], [%1], 16;" :: "r"(dst), "l"(src) : "memory")
#define CP_COMMIT() asm volatile("cp.async.commit_group;" ::: "memory")
#define CP_WAIT2()  asm volatile("cp.async.wait_group 2;" ::: "memory")

#define LDMATRIX_X4(r0, r1, r2, r3, addr) \
    asm volatile("ldmatrix.sync.aligned.m8n8.x4.shared.b16 {%0,%1,%2,%3}, [%4];" \
                 : "=r"(r0), "=r"(r1), "=r"(r2), "=r"(r3) : "r"(addr))
#define LDMATRIX_X4_T(r0, r1, r2, r3, addr) \
    asm volatile("ldmatrix.sync.aligned.m8n8.x4.trans.shared.b16 {%0,%1,%2,%3}, [%4];" \
                 : "=r"(r0), "=r"(r1), "=r"(r2), "=r"(r3) : "r"(addr))

#define MMA_BF16(c, a, b0, b1) \
    asm volatile("mma.sync.aligned.m16n8k16.row.col.f32.bf16.bf16.f32 " \
                 "{%0,%1,%2,%3}, {%4,%5,%6,%7}, {%8,%9}, {%0,%1,%2,%3};" \
                 : "+f"((c)[0]), "+f"((c)[1]), "+f"((c)[2]), "+f"((c)[3]) \
                 : "r"((a)[0]), "r"((a)[1]), "r"((a)[2]), "r"((a)[3]), "r"(b0), "r"(b1))

__device__ __forceinline__ void split2(float a, float b, uint32_t& hi, uint32_t& lo) {
    __nv_bfloat16 ha = __float2bfloat16_rn(a), hb = __float2bfloat16_rn(b);
    float la = a - __bfloat162float(ha), lb = b - __bfloat162float(hb);
    __nv_bfloat162 hv = __halves2bfloat162(ha, hb);
    __nv_bfloat162 lv = __halves2bfloat162(__float2bfloat16_rn(la), __float2bfloat16_rn(lb));
    hi = *(uint32_t*)&hv;
    lo = *(uint32_t*)&lv;
}

// ================== bias table =============================================
__device__ __forceinline__ int bucket_of(int rp) {
    int b = (rp > 0) ? 16 : 0;
    int a = rp < 0 ? -rp : rp;
    if (a < 8) return b + a;
    double v = 7.0 + (log((double)a / 7.0) / log(128.0 / 7.0)) * 8.0;
    int large = (int)v;
    if (large > 15) large = 15;
    return b + large;
}
__global__ void bias_kernel(const float* __restrict__ rel_emb, float* __restrict__ btab) {
    int idx = blockIdx.x * blockDim.x + threadIdx.x;
    if (idx >= NH_ * NBIAS) return;
    int h = idx / NBIAS;
    int x = idx % NBIAS;
    btab[idx] = rel_emb[bucket_of(x - (T_ - 1)) * NH_ + h];
}

// ================== fp32 -> 3-segment split-bf16 ===========================
template <int MODE>
__global__ void split3_kernel(const float* __restrict__ in, __nv_bfloat16* __restrict__ out,
                              int nrows) {
    int i = blockIdx.x * blockDim.x + threadIdx.x;
    if (i >= nrows * (D_ / 4)) return;
    int r = i / (D_ / 4);
    int c = (i % (D_ / 4)) * 4;
    float4 v = *(const float4*)(in + (size_t)r * D_ + c);
    uint32_t h0, l0, h1, l1;
    split2(v.x, v.y, h0, l0);
    split2(v.z, v.w, h1, l1);
    uint32_t* base = (uint32_t*)(out + (size_t)r * K3_ + c);
    base[0] = h0; base[1] = h1;
    uint32_t* s1 = (uint32_t*)(out + (size_t)r * K3_ + D_ + c);
    uint32_t* s2 = (uint32_t*)(out + (size_t)r * K3_ + 2 * D_ + c);
    if (MODE == 0) { s1[0] = h0; s1[1] = h1; s2[0] = l0; s2[1] = l1; }
    else           { s1[0] = l0; s1[1] = l1; s2[0] = h0; s2[1] = h1; }
}

// ================== HMMA bf16 GEMM v2 ======================================
// CTA 128x128x32, 128 thr (4 warps, warp tile 64x64), 4-stage cp.async,
// 2 CTAs/SM. grid.z selects weight/out (QKV fused launch).
#define BK_ 32
#define GS2 4
#define TB2 8192                    // 8KB per operand tile per stage
#define ST2 (2 * TB2)               // 16KB per stage
#define GEMM2_SMEM (GS2 * ST2)      // 64KB
#define GITERS (K3_ / BK_)          // 96
#define WOFF ((size_t)D_ * K3_)

__global__ __launch_bounds__(128, 2)
void gemm_hmma2(const __nv_bfloat16* __restrict__ A, const __nv_bfloat16* __restrict__ W0,
                float* __restrict__ o0, float* __restrict__ o1, float* __restrict__ o2) {
    extern __shared__ char sm[];
    const uint32_t sb = smem_u32(sm);

    const int tid  = threadIdx.x;
    const int w    = tid >> 5;
    const int lane = tid & 31;
    const int wm   = w >> 1;           // 0..1: 64-row half
    const int wn   = w & 1;            // 0..1: 64-col half
    const int m0   = blockIdx.y * 128;
    const int n0   = blockIdx.x * 128;
    const int z    = blockIdx.z;
    const __nv_bfloat16* W = W0 + (size_t)z * WOFF;
    float* out = (z == 0) ? o0 : (z == 1) ? o1 : o2;

    float acc[4][8][4];
#pragma unroll
    for (int i = 0; i < 4; i++)
#pragma unroll
        for (int j = 0; j < 8; j++)
#pragma unroll
            for (int q = 0; q < 4; q++) acc[i][j][q] = 0.f;

    // loader: stage it -> slot it&3; each thread loads one 64B row of A and B
    auto load_stage = [&](int it) {
        const uint32_t st = sb + (uint32_t)(it & 3) * ST2;
        const int kb = it * BK_;
        const int sw = (tid >> 1) & 3;
#pragma unroll
        for (int j = 0; j < 4; j++) {
            uint32_t dst = st + tid * 64 + ((j ^ sw) << 4);
            CP_ASYNC16(dst, (const void*)(A + (size_t)(m0 + tid) * K3_ + kb + j * 8));
        }
#pragma unroll
        for (int j = 0; j < 4; j++) {
            uint32_t dst = st + TB2 + tid * 64 + ((j ^ sw) << 4);
            CP_ASYNC16(dst, (const void*)(W + (size_t)(n0 + tid) * K3_ + kb + j * 8));
        }
        CP_COMMIT();
    };

    load_stage(0);
    load_stage(1);
    load_stage(2);

    for (int it = 0; it < GITERS; it++) {
        CP_WAIT2();                      // <=2 groups pending -> stage it complete
        __syncthreads();                 // also guards stage (it-1)%4 overwrite below
        if (it + 3 < GITERS) load_stage(it + 3);
        else CP_COMMIT();

        const uint32_t aB = sb + (uint32_t)(it & 3) * ST2;
        const uint32_t bB = aB + TB2;

#pragma unroll
        for (int ks = 0; ks < 2; ks++) {
            uint32_t a[4][4];
#pragma unroll
            for (int fm = 0; fm < 4; fm++) {
                int row = wm * 64 + fm * 16 + (lane & 15);
                int u = ks * 2 + (lane >> 4);
                uint32_t ad = aB + row * 64 + ((u ^ ((row >> 1) & 3)) << 4);
                LDMATRIX_X4(a[fm][0], a[fm][1], a[fm][2], a[fm][3], ad);
            }
            uint32_t b[4][4];
#pragma unroll
            for (int fp = 0; fp < 4; fp++) {
                int n = wn * 64 + fp * 16 + (lane & 7) + ((lane >> 4) << 3);
                int u = ks * 2 + ((lane >> 3) & 1);
                uint32_t bd = bB + n * 64 + ((u ^ ((n >> 1) & 3)) << 4);
                LDMATRIX_X4(b[fp][0], b[fp][1], b[fp][2], b[fp][3], bd);
            }
#pragma unroll
            for (int fm = 0; fm < 4; fm++)
#pragma unroll
                for (int fp = 0; fp < 4; fp++) {
                    MMA_BF16(acc[fm][fp * 2 + 0], a[fm], b[fp][0], b[fp][1]);
                    MMA_BF16(acc[fm][fp * 2 + 1], a[fm], b[fp][2], b[fp][3]);
                }
        }
    }

    const int cr = lane >> 2;
    const int cc = 2 * (lane & 3);
#pragma unroll
    for (int fm = 0; fm < 4; fm++) {
        int r = m0 + wm * 64 + fm * 16 + cr;
#pragma unroll
        for (int fn = 0; fn < 8; fn++) {
            int col = n0 + wn * 64 + fn * 8 + cc;
            *(float2*)(out + (size_t)r * D_ + col) =
                make_float2(acc[fm][fn][0], acc[fm][fn][1]);
            *(float2*)(out + (size_t)(r + 8) * D_ + col) =
                make_float2(acc[fm][fn][2], acc[fm][fn][3]);
        }
    }
}

// ================== HMMA flash attention ===================================
// (unchanged compute; epilogue now writes split-bf16 AO3 [hi|hi|lo] directly)
#define QT 128
#define KT 64
#define ASM_Q 0u
#define ASM_K 32768u
#define ASM_V 49152u
#define ATTN_SMEM 65536

__global__ __launch_bounds__(256, 2)
void attn_hmma(const float* __restrict__ Q, const float* __restrict__ K,
               const float* __restrict__ V, const float* __restrict__ btab,
               __nv_bfloat16* __restrict__ out3) {
    extern __shared__ char sm[];
    const uint32_t sb = smem_u32(sm);

    const int tid  = threadIdx.x;
    const int w    = tid >> 5;
    const int lane = tid & 31;
    const int bh = blockIdx.y;
    const int h  = bh & (NH_ - 1);
    const int b  = bh >> 4;
    const int q0 = blockIdx.x * QT;

    const float* Qb = Q + (size_t)b * T_ * D_ + h * HS_;
    const float* Kb = K + (size_t)b * T_ * D_ + h * HS_;
    const float* Vb = V + (size_t)b * T_ * D_ + h * HS_;
    const float* bias_h = btab + h * NBIAS + (T_ - 1);

#pragma unroll
    for (int i = tid; i < QT * 16; i += 256) {
        int row = i >> 4, g = i & 15;
        float4 v = *(const float4*)(Qb + (size_t)(q0 + row) * D_ + 4 * g);
        uint32_t h0, l0, h1, l1;
        split2(v.x * 0.125f, v.y * 0.125f, h0, l0);
        split2(v.z * 0.125f, v.w * 0.125f, h1, l1);
        char* rp = sm + ASM_Q + row * 256;
        int su0 = ((g >> 1) ^ row) & 7;
        *(uint32_t*)(rp + su0 * 16 + ((8 * g) & 15))     = h0;
        *(uint32_t*)(rp + su0 * 16 + ((8 * g + 4) & 15)) = h1;
        int su1 = 8 | (((8 + (g >> 1)) ^ row) & 7);
        *(uint32_t*)(rp + su1 * 16 + ((8 * g) & 15))     = l0;
        *(uint32_t*)(rp + su1 * 16 + ((8 * g + 4) & 15)) = l1;
    }

    float ofr[8][4];
    float mrow[2] = {-1e30f, -1e30f};
    float lrow[2] = {0.f, 0.f};
#pragma unroll
    for (int j = 0; j < 8; j++)
#pragma unroll
        for (int q = 0; q < 4; q++) ofr[j][q] = 0.f;

    for (int k0 = 0; k0 < T_; k0 += KT) {
        __syncthreads();
#pragma unroll
        for (int i = tid; i < KT * 16; i += 256) {
            int row = i >> 4, g = i & 15;
            float4 v = *(const float4*)(Kb + (size_t)(k0 + row) * D_ + 4 * g);
            uint32_t h0, l0, h1, l1;
            split2(v.x, v.y, h0, l0);
            split2(v.z, v.w, h1, l1);
            char* rp = sm + ASM_K + row * 256;
            int su0 = ((g >> 1) ^ row) & 7;
            *(uint32_t*)(rp + su0 * 16 + ((8 * g) & 15))     = h0;
            *(uint32_t*)(rp + su0 * 16 + ((8 * g + 4) & 15)) = h1;
            int su1 = 8 | (((8 + (g >> 1)) ^ row) & 7);
            *(uint32_t*)(rp + su1 * 16 + ((8 * g) & 15))     = l0;
            *(uint32_t*)(rp + su1 * 16 + ((8 * g + 4) & 15)) = l1;
        }
#pragma unroll
        for (int i = tid; i < KT * 16; i += 256) {
            int key = i >> 4, g = i & 15;
            float4 v = *(const float4*)(Vb + (size_t)(k0 + key) * D_ + 4 * g);
            uint32_t h0, l0, h1, l1;
            split2(v.x, v.y, h0, l0);
            split2(v.z, v.w, h1, l1);
            int u = g >> 1;
            char* rh = sm + ASM_V + key * 128;
            int suh = (u ^ (key & 7));
            *(uint32_t*)(rh + suh * 16 + ((8 * g) & 15))     = h0;
            *(uint32_t*)(rh + suh * 16 + ((8 * g + 4) & 15)) = h1;
            char* rl = sm + ASM_V + (64 + key) * 128;
            *(uint32_t*)(rl + suh * 16 + ((8 * g) & 15))     = l0;
            *(uint32_t*)(rl + suh * 16 + ((8 * g + 4) & 15)) = l1;
        }
        __syncthreads();

        float sf[8][4];
#pragma unroll
        for (int j = 0; j < 8; j++)
#pragma unroll
            for (int q = 0; q < 4; q++) sf[j][q] = 0.f;

#pragma unroll
        for (int u = 0; u < 4; u++) {
            uint32_t ah[4], al[4];
            {
                int row = w * 16 + (lane & 15);
                int uh = 2 * u + (lane >> 4);
                uint32_t adh = sb + ASM_Q + row * 256 + (((uh ^ row) & 7) << 4);
                LDMATRIX_X4(ah[0], ah[1], ah[2], ah[3], adh);
                int ul = 8 + 2 * u + (lane >> 4);
                uint32_t adl = sb + ASM_Q + row * 256 + ((8 | ((ul ^ row) & 7)) << 4);
                LDMATRIX_X4(al[0], al[1], al[2], al[3], adl);
            }
#pragma unroll
            for (int fp = 0; fp < 4; fp++) {
                int n = fp * 16 + (lane & 7) + ((lane >> 4) << 3);
                int uh = 2 * u + ((lane >> 3) & 1);
                uint32_t bh_[4], bl_[4];
                uint32_t bdh = sb + ASM_K + n * 256 + (((uh ^ n) & 7) << 4);
                LDMATRIX_X4(bh_[0], bh_[1], bh_[2], bh_[3], bdh);
                int ul = 8 + 2 * u + ((lane >> 3) & 1);
                uint32_t bdl = sb + ASM_K + n * 256 + ((8 | ((ul ^ n) & 7)) << 4);
                LDMATRIX_X4(bl_[0], bl_[1], bl_[2], bl_[3], bdl);
                MMA_BF16(sf[2 * fp + 0], ah, bh_[0], bh_[1]);
                MMA_BF16(sf[2 * fp + 1], ah, bh_[2], bh_[3]);
                MMA_BF16(sf[2 * fp + 0], ah, bl_[0], bl_[1]);
                MMA_BF16(sf[2 * fp + 1], ah, bl_[2], bl_[3]);
                MMA_BF16(sf[2 * fp + 0], al, bh_[0], bh_[1]);
                MMA_BF16(sf[2 * fp + 1], al, bh_[2], bh_[3]);
            }
        }

        const int r0g = q0 + w * 16 + (lane >> 2);
#pragma unroll
        for (int j = 0; j < 8; j++) {
            int dk = k0 + 8 * j + 2 * (lane & 3) - r0g;
            sf[j][0] += bias_h[dk];
            sf[j][1] += bias_h[dk + 1];
            sf[j][2] += bias_h[dk - 8];
            sf[j][3] += bias_h[dk - 7];
        }

        float mt0 = -1e30f, mt1 = -1e30f;
#pragma unroll
        for (int j = 0; j < 8; j++) {
            mt0 = fmaxf(mt0, fmaxf(sf[j][0], sf[j][1]));
            mt1 = fmaxf(mt1, fmaxf(sf[j][2], sf[j][3]));
        }
        mt0 = fmaxf(mt0, __shfl_xor_sync(0xffffffffu, mt0, 1));
        mt0 = fmaxf(mt0, __shfl_xor_sync(0xffffffffu, mt0, 2));
        mt1 = fmaxf(mt1, __shfl_xor_sync(0xffffffffu, mt1, 1));
        mt1 = fmaxf(mt1, __shfl_xor_sync(0xffffffffu, mt1, 2));

        float mn0 = fmaxf(mrow[0], mt0), mn1 = fmaxf(mrow[1], mt1);
        float alpha0 = __expf(mrow[0] - mn0), alpha1 = __expf(mrow[1] - mn1);
        mrow[0] = mn0; mrow[1] = mn1;

        float ls0 = 0.f, ls1 = 0.f;
#pragma unroll
        for (int j = 0; j < 8; j++) {
            sf[j][0] = __expf(sf[j][0] - mn0);
            sf[j][1] = __expf(sf[j][1] - mn0);
            sf[j][2] = __expf(sf[j][2] - mn1);
            sf[j][3] = __expf(sf[j][3] - mn1);
            ls0 += sf[j][0] + sf[j][1];
            ls1 += sf[j][2] + sf[j][3];
        }
        ls0 += __shfl_xor_sync(0xffffffffu, ls0, 1);
        ls0 += __shfl_xor_sync(0xffffffffu, ls0, 2);
        ls1 += __shfl_xor_sync(0xffffffffu, ls1, 1);
        ls1 += __shfl_xor_sync(0xffffffffu, ls1, 2);
        lrow[0] = lrow[0] * alpha0 + ls0;
        lrow[1] = lrow[1] * alpha1 + ls1;
#pragma unroll
        for (int j = 0; j < 8; j++) {
            ofr[j][0] *= alpha0; ofr[j][1] *= alpha0;
            ofr[j][2] *= alpha1; ofr[j][3] *= alpha1;
        }

#pragma unroll
        for (int kk = 0; kk < 4; kk++) {
            uint32_t ph[4], pl[4];
            split2(sf[2 * kk][0],     sf[2 * kk][1],     ph[0], pl[0]);
            split2(sf[2 * kk][2],     sf[2 * kk][3],     ph[1], pl[1]);
            split2(sf[2 * kk + 1][0], sf[2 * kk + 1][1], ph[2], pl[2]);
            split2(sf[2 * kk + 1][2], sf[2 * kk + 1][3], ph[3], pl[3]);
            const int g = lane >> 3;
            const int rowh = kk * 16 + ((g & 1) << 3) + (lane & 7);
            const int rowl = 64 + rowh;
#pragma unroll
            for (int fb = 0; fb < 4; fb++) {
                int unit = fb * 2 + (g >> 1);
                uint32_t bvh[4], bvl[4];
                uint32_t avh = sb + ASM_V + rowh * 128 + ((unit ^ (rowh & 7)) << 4);
                LDMATRIX_X4_T(bvh[0], bvh[1], bvh[2], bvh[3], avh);
                uint32_t avl = sb + ASM_V + rowl * 128 + ((unit ^ (rowl & 7)) << 4);
                LDMATRIX_X4_T(bvl[0], bvl[1], bvl[2], bvl[3], avl);
                MMA_BF16(ofr[2 * fb + 0], ph, bvh[0], bvh[1]);
                MMA_BF16(ofr[2 * fb + 1], ph, bvh[2], bvh[3]);
                MMA_BF16(ofr[2 * fb + 0], ph, bvl[0], bvl[1]);
                MMA_BF16(ofr[2 * fb + 1], ph, bvl[2], bvl[3]);
                MMA_BF16(ofr[2 * fb + 0], pl, bvh[0], bvh[1]);
                MMA_BF16(ofr[2 * fb + 1], pl, bvh[2], bvh[3]);
            }
        }
    }

    // ---- epilogue: write split-bf16 AO3 directly ([hi | hi | lo]) ----
    const float inv0 = 1.f / lrow[0], inv1 = 1.f / lrow[1];
    const int r0 = q0 + w * 16 + (lane >> 2), r1 = r0 + 8;
    __nv_bfloat16* row0 = out3 + (size_t)(b * T_ + r0) * K3_;
    __nv_bfloat16* row1 = out3 + (size_t)(b * T_ + r1) * K3_;
#pragma unroll
    for (int j = 0; j < 8; j++) {
        int col = h * HS_ + 8 * j + 2 * (lane & 3);
        uint32_t hi, lo;
        split2(ofr[j][0] * inv0, ofr[j][1] * inv0, hi, lo);
        *(uint32_t*)(row0 + col)          = hi;
        *(uint32_t*)(row0 + D_ + col)     = hi;
        *(uint32_t*)(row0 + 2 * D_ + col) = lo;
        split2(ofr[j][2] * inv1, ofr[j][3] * inv1, hi, lo);
        *(uint32_t*)(row1 + col)          = hi;
        *(uint32_t*)(row1 + D_ + col)     = hi;
        *(uint32_t*)(row1 + 2 * D_ + col) = lo;
    }
}

// ================== launch ==================================================
extern "C" void kernel_launch(void* const* d_in, const int* in_sizes, int n_in,
                              void* d_out, int out_size) {
    const float* queries = (const float*)d_in[0];
    const float* Wq      = (const float*)d_in[1];
    const float* Wk      = (const float*)d_in[2];
    const float* Wv      = (const float*)d_in[3];
    const float* Wo      = (const float*)d_in[4];
    const float* rel_emb = (const float*)d_in[5];
    float* out = (float*)d_out;

    __nv_bfloat16 *gA3, *gAO3, *gW3;
    float *gQ, *gK, *gV, *gB;
    cudaGetSymbolAddress((void**)&gA3,  g_A3);
    cudaGetSymbolAddress((void**)&gAO3, g_AO3);
    cudaGetSymbolAddress((void**)&gW3,  g_W3);
    cudaGetSymbolAddress((void**)&gQ,   g_Q);
    cudaGetSymbolAddress((void**)&gK,   g_K);
    cudaGetSymbolAddress((void**)&gV,   g_V);
    cudaGetSymbolAddress((void**)&gB,   g_bias);

    cudaFuncSetAttribute(attn_hmma,  cudaFuncAttributeMaxDynamicSharedMemorySize, ATTN_SMEM);
    cudaFuncSetAttribute(gemm_hmma2, cudaFuncAttributeMaxDynamicSharedMemorySize, GEMM2_SMEM);

    bias_kernel<<<(NH_ * NBIAS + 255) / 256, 256>>>(rel_emb, gB);
    split3_kernel<0><<<(M_ * (D_ / 4) + 255) / 256, 256>>>(queries, gA3, M_);
    split3_kernel<1><<<(D_ * (D_ / 4) + 255) / 256, 256>>>(Wq, gW3 + 0 * WOFF, D_);
    split3_kernel<1><<<(D_ * (D_ / 4) + 255) / 256, 256>>>(Wk, gW3 + 1 * WOFF, D_);
    split3_kernel<1><<<(D_ * (D_ / 4) + 255) / 256, 256>>>(Wv, gW3 + 2 * WOFF, D_);
    split3_kernel<1><<<(D_ * (D_ / 4) + 255) / 256, 256>>>(Wo, gW3 + 3 * WOFF, D_);

    // fused Q/K/V projections (grid.z picks weight + output)
    dim3 gGrid(D_ / 128, M_ / 128, 3);
    gemm_hmma2<<<gGrid, 128, GEMM2_SMEM>>>(gA3, gW3, gQ, gK, gV);

    // attention -> split AO3 directly
    dim3 aGrid(T_ / QT, B_ * NH_);
    attn_hmma<<<aGrid, 256, ATTN_SMEM>>>(gQ, gK, gV, gB, gAO3);

    // output projection
    dim3 oGrid(D_ / 128, M_ / 128, 1);
    gemm_hmma2<<<oGrid, 128, GEMM2_SMEM>>>(gAO3, gW3 + 3 * WOFF, out, out, out);
}

// round 6
// speedup vs baseline: 3.1388x; 1.1916x over previous
#include <cuda_runtime.h>
#include <cuda_bf16.h>
#include <math.h>
#include <stdint.h>

#define B_  4
#define T_  2048
#define D_  1024
#define NH_ 16
#define HS_ 64
#define NBIAS (2*T_ - 1)   // 4095
#define M_  (B_*T_)        // 8192
#define K3_ 3072           // split-bf16 K: [hi | hi | lo] x [hi | lo | hi]

// ---------------- scratch (device globals: no allocation allowed) ----------
__device__ __nv_bfloat16 g_A3 [M_*(size_t)K3_];
__device__ __nv_bfloat16 g_AO3[M_*(size_t)K3_];
__device__ __nv_bfloat16 g_W3 [4*(size_t)D_*K3_];
__device__ float g_Q [M_*(size_t)D_];              // row-major [b*t, d]
__device__ float g_K [M_*(size_t)D_];
__device__ float g_V [M_*(size_t)D_];
__device__ float g_bias[NH_*NBIAS];

// ============================ PTX helpers ==================================
__device__ __forceinline__ uint32_t smem_u32(const void* p) {
    uint32_t a;
    asm("{ .reg .u64 t; cvta.to.shared.u64 t, %1; cvt.u32.u64 %0, t; }" : "=r"(a) : "l"(p));
    return a;
}
#define CP_ASYNC16(dst, src) \
    asm volatile("cp.async.cg.shared.global [%0], [%1], 16;" :: "r"(dst), "l"(src) : "memory")
#define CP_COMMIT() asm volatile("cp.async.commit_group;" ::: "memory")
#define CP_WAIT3()  asm volatile("cp.async.wait_group 3;" ::: "memory")

#define LDMATRIX_X4(r0, r1, r2, r3, addr) \
    asm volatile("ldmatrix.sync.aligned.m8n8.x4.shared.b16 {%0,%1,%2,%3}, [%4];" \
                 : "=r"(r0), "=r"(r1), "=r"(r2), "=r"(r3) : "r"(addr))
#define LDMATRIX_X4_T(r0, r1, r2, r3, addr) \
    asm volatile("ldmatrix.sync.aligned.m8n8.x4.trans.shared.b16 {%0,%1,%2,%3}, [%4];" \
                 : "=r"(r0), "=r"(r1), "=r"(r2), "=r"(r3) : "r"(addr))

#define MMA_BF16(c, a, b0, b1) \
    asm volatile("mma.sync.aligned.m16n8k16.row.col.f32.bf16.bf16.f32 " \
                 "{%0,%1,%2,%3}, {%4,%5,%6,%7}, {%8,%9}, {%0,%1,%2,%3};" \
                 : "+f"((c)[0]), "+f"((c)[1]), "+f"((c)[2]), "+f"((c)[3]) \
                 : "r"((a)[0]), "r"((a)[1]), "r"((a)[2]), "r"((a)[3]), "r"(b0), "r"(b1))

__device__ __forceinline__ void split2(float a, float b, uint32_t& hi, uint32_t& lo) {
    __nv_bfloat16 ha = __float2bfloat16_rn(a), hb = __float2bfloat16_rn(b);
    float la = a - __bfloat162float(ha), lb = b - __bfloat162float(hb);
    __nv_bfloat162 hv = __halves2bfloat162(ha, hb);
    __nv_bfloat162 lv = __halves2bfloat162(__float2bfloat16_rn(la), __float2bfloat16_rn(lb));
    hi = *(uint32_t*)&hv;
    lo = *(uint32_t*)&lv;
}

// ================== bias table =============================================
__device__ __forceinline__ int bucket_of(int rp) {
    int b = (rp > 0) ? 16 : 0;
    int a = rp < 0 ? -rp : rp;
    if (a < 8) return b + a;
    double v = 7.0 + (log((double)a / 7.0) / log(128.0 / 7.0)) * 8.0;
    int large = (int)v;
    if (large > 15) large = 15;
    return b + large;
}
__global__ void bias_kernel(const float* __restrict__ rel_emb, float* __restrict__ btab) {
    int idx = blockIdx.x * blockDim.x + threadIdx.x;
    if (idx >= NH_ * NBIAS) return;
    int h = idx / NBIAS;
    int x = idx % NBIAS;
    btab[idx] = rel_emb[bucket_of(x - (T_ - 1)) * NH_ + h];
}

// ================== fp32 -> 3-segment split-bf16 ===========================
template <int MODE>
__global__ void split3_kernel(const float* __restrict__ in, __nv_bfloat16* __restrict__ out,
                              int nrows) {
    int i = blockIdx.x * blockDim.x + threadIdx.x;
    if (i >= nrows * (D_ / 4)) return;
    int r = i / (D_ / 4);
    int c = (i % (D_ / 4)) * 4;
    float4 v = *(const float4*)(in + (size_t)r * D_ + c);
    uint32_t h0, l0, h1, l1;
    split2(v.x, v.y, h0, l0);
    split2(v.z, v.w, h1, l1);
    uint32_t* base = (uint32_t*)(out + (size_t)r * K3_ + c);
    base[0] = h0; base[1] = h1;
    uint32_t* s1 = (uint32_t*)(out + (size_t)r * K3_ + D_ + c);
    uint32_t* s2 = (uint32_t*)(out + (size_t)r * K3_ + 2 * D_ + c);
    if (MODE == 0) { s1[0] = h0; s1[1] = h1; s2[0] = l0; s2[1] = l1; }
    else           { s1[0] = l0; s1[1] = l1; s2[0] = h0; s2[1] = h1; }
}

// ================== HMMA bf16 GEMM v3 ======================================
// CTA 128x128x32, 256 thr (8 warps, warp tile 64x32), 5-stage cp.async,
// one sync/iter, 2 CTAs/SM (16 warps/SM). grid.z selects weight/out.
#define BK_ 32
#define GS3 5
#define TB3 8192                    // 8KB per operand tile per stage
#define ST3 (2 * TB3)               // 16KB per stage
#define GEMM3_SMEM (GS3 * ST3)      // 80KB
#define GITERS (K3_ / BK_)          // 96
#define WOFF ((size_t)D_ * K3_)

__global__ __launch_bounds__(256, 2)
void gemm_hmma3(const __nv_bfloat16* __restrict__ A, const __nv_bfloat16* __restrict__ W0,
                float* __restrict__ o0, float* __restrict__ o1, float* __restrict__ o2) {
    extern __shared__ char sm3[];
    const uint32_t sb = smem_u32(sm3);

    const int tid  = threadIdx.x;
    const int w    = tid >> 5;
    const int lane = tid & 31;
    const int wm   = w & 1;            // 0..1: 64-row half
    const int wn   = w >> 1;           // 0..3: 32-col quarter
    const int m0   = blockIdx.y * 128;
    const int n0   = blockIdx.x * 128;
    const int z    = blockIdx.z;
    const __nv_bfloat16* W = W0 + (size_t)z * WOFF;
    float* out = (z == 0) ? o0 : (z == 1) ? o1 : o2;

    float acc[4][4][4];
#pragma unroll
    for (int i = 0; i < 4; i++)
#pragma unroll
        for (int j = 0; j < 4; j++)
#pragma unroll
            for (int q = 0; q < 4; q++) acc[i][j][q] = 0.f;

    // loader: stage it -> slot it%5; 512 16B-units per operand / 256 thr
    auto load_stage = [&](int it) {
        const uint32_t st = sb + (uint32_t)(it % GS3) * ST3;
        const int kb = it * BK_;
#pragma unroll
        for (int j = 0; j < 2; j++) {
            int idx = tid * 2 + j;
            int row = idx >> 2, u = idx & 3;
            uint32_t dst = st + row * 64 + ((u ^ ((row >> 1) & 3)) << 4);
            CP_ASYNC16(dst, (const void*)(A + (size_t)(m0 + row) * K3_ + kb + u * 8));
        }
#pragma unroll
        for (int j = 0; j < 2; j++) {
            int idx = tid * 2 + j;
            int row = idx >> 2, u = idx & 3;
            uint32_t dst = st + TB3 + row * 64 + ((u ^ ((row >> 1) & 3)) << 4);
            CP_ASYNC16(dst, (const void*)(W + (size_t)(n0 + row) * K3_ + kb + u * 8));
        }
        CP_COMMIT();
    };

    load_stage(0);
    load_stage(1);
    load_stage(2);
    load_stage(3);

    for (int it = 0; it < GITERS; it++) {
        CP_WAIT3();                      // <=3 groups pending -> stage it complete
        __syncthreads();                 // guards slot (it+4)%5 == (it-1)%5 overwrite
        if (it + 4 < GITERS) load_stage(it + 4);
        else CP_COMMIT();

        const uint32_t aB = sb + (uint32_t)(it % GS3) * ST3;
        const uint32_t bB = aB + TB3;

#pragma unroll
        for (int ks = 0; ks < 2; ks++) {
            uint32_t a[4][4];
#pragma unroll
            for (int fm = 0; fm < 4; fm++) {
                int row = wm * 64 + fm * 16 + (lane & 15);
                int u = ks * 2 + (lane >> 4);
                uint32_t ad = aB + row * 64 + ((u ^ ((row >> 1) & 3)) << 4);
                LDMATRIX_X4(a[fm][0], a[fm][1], a[fm][2], a[fm][3], ad);
            }
            uint32_t b[2][4];
#pragma unroll
            for (int fp = 0; fp < 2; fp++) {
                int n = wn * 32 + fp * 16 + (lane & 7) + ((lane >> 4) << 3);
                int u = ks * 2 + ((lane >> 3) & 1);
                uint32_t bd = bB + n * 64 + ((u ^ ((n >> 1) & 3)) << 4);
                LDMATRIX_X4(b[fp][0], b[fp][1], b[fp][2], b[fp][3], bd);
            }
#pragma unroll
            for (int fm = 0; fm < 4; fm++)
#pragma unroll
                for (int fp = 0; fp < 2; fp++) {
                    MMA_BF16(acc[fm][fp * 2 + 0], a[fm], b[fp][0], b[fp][1]);
                    MMA_BF16(acc[fm][fp * 2 + 1], a[fm], b[fp][2], b[fp][3]);
                }
        }
    }

    const int cr = lane >> 2;
    const int cc = 2 * (lane & 3);
#pragma unroll
    for (int fm = 0; fm < 4; fm++) {
        int r = m0 + wm * 64 + fm * 16 + cr;
#pragma unroll
        for (int fn = 0; fn < 4; fn++) {
            int col = n0 + wn * 32 + fn * 8 + cc;
            *(float2*)(out + (size_t)r * D_ + col) =
                make_float2(acc[fm][fn][0], acc[fm][fn][1]);
            *(float2*)(out + (size_t)(r + 8) * D_ + col) =
                make_float2(acc[fm][fn][2], acc[fm][fn][3]);
        }
    }
}

// ================== HMMA flash attention ===================================
#define QT 128
#define KT 64
#define ASM_Q 0u
#define ASM_K 32768u
#define ASM_V 49152u
#define ATTN_SMEM 65536

__global__ __launch_bounds__(256, 2)
void attn_hmma(const float* __restrict__ Q, const float* __restrict__ K,
               const float* __restrict__ V, const float* __restrict__ btab,
               __nv_bfloat16* __restrict__ out3) {
    extern __shared__ char sm[];
    const uint32_t sb = smem_u32(sm);

    const int tid  = threadIdx.x;
    const int w    = tid >> 5;
    const int lane = tid & 31;
    const int bh = blockIdx.y;
    const int h  = bh & (NH_ - 1);
    const int b  = bh >> 4;
    const int q0 = blockIdx.x * QT;

    const float* Qb = Q + (size_t)b * T_ * D_ + h * HS_;
    const float* Kb = K + (size_t)b * T_ * D_ + h * HS_;
    const float* Vb = V + (size_t)b * T_ * D_ + h * HS_;
    const float* bias_h = btab + h * NBIAS + (T_ - 1);

#pragma unroll
    for (int i = tid; i < QT * 16; i += 256) {
        int row = i >> 4, g = i & 15;
        float4 v = *(const float4*)(Qb + (size_t)(q0 + row) * D_ + 4 * g);
        uint32_t h0, l0, h1, l1;
        split2(v.x * 0.125f, v.y * 0.125f, h0, l0);
        split2(v.z * 0.125f, v.w * 0.125f, h1, l1);
        char* rp = sm + ASM_Q + row * 256;
        int su0 = ((g >> 1) ^ row) & 7;
        *(uint32_t*)(rp + su0 * 16 + ((8 * g) & 15))     = h0;
        *(uint32_t*)(rp + su0 * 16 + ((8 * g + 4) & 15)) = h1;
        int su1 = 8 | (((8 + (g >> 1)) ^ row) & 7);
        *(uint32_t*)(rp + su1 * 16 + ((8 * g) & 15))     = l0;
        *(uint32_t*)(rp + su1 * 16 + ((8 * g + 4) & 15)) = l1;
    }

    float ofr[8][4];
    float mrow[2] = {-1e30f, -1e30f};
    float lrow[2] = {0.f, 0.f};
#pragma unroll
    for (int j = 0; j < 8; j++)
#pragma unroll
        for (int q = 0; q < 4; q++) ofr[j][q] = 0.f;

    for (int k0 = 0; k0 < T_; k0 += KT) {
        __syncthreads();
#pragma unroll
        for (int i = tid; i < KT * 16; i += 256) {
            int row = i >> 4, g = i & 15;
            float4 v = *(const float4*)(Kb + (size_t)(k0 + row) * D_ + 4 * g);
            uint32_t h0, l0, h1, l1;
            split2(v.x, v.y, h0, l0);
            split2(v.z, v.w, h1, l1);
            char* rp = sm + ASM_K + row * 256;
            int su0 = ((g >> 1) ^ row) & 7;
            *(uint32_t*)(rp + su0 * 16 + ((8 * g) & 15))     = h0;
            *(uint32_t*)(rp + su0 * 16 + ((8 * g + 4) & 15)) = h1;
            int su1 = 8 | (((8 + (g >> 1)) ^ row) & 7);
            *(uint32_t*)(rp + su1 * 16 + ((8 * g) & 15))     = l0;
            *(uint32_t*)(rp + su1 * 16 + ((8 * g + 4) & 15)) = l1;
        }
#pragma unroll
        for (int i = tid; i < KT * 16; i += 256) {
            int key = i >> 4, g = i & 15;
            float4 v = *(const float4*)(Vb + (size_t)(k0 + key) * D_ + 4 * g);
            uint32_t h0, l0, h1, l1;
            split2(v.x, v.y, h0, l0);
            split2(v.z, v.w, h1, l1);
            int u = g >> 1;
            char* rh = sm + ASM_V + key * 128;
            int suh = (u ^ (key & 7));
            *(uint32_t*)(rh + suh * 16 + ((8 * g) & 15))     = h0;
            *(uint32_t*)(rh + suh * 16 + ((8 * g + 4) & 15)) = h1;
            char* rl = sm + ASM_V + (64 + key) * 128;
            *(uint32_t*)(rl + suh * 16 + ((8 * g) & 15))     = l0;
            *(uint32_t*)(rl + suh * 16 + ((8 * g + 4) & 15)) = l1;
        }
        __syncthreads();

        float sf[8][4];
#pragma unroll
        for (int j = 0; j < 8; j++)
#pragma unroll
            for (int q = 0; q < 4; q++) sf[j][q] = 0.f;

#pragma unroll
        for (int u = 0; u < 4; u++) {
            uint32_t ah[4], al[4];
            {
                int row = w * 16 + (lane & 15);
                int uh = 2 * u + (lane >> 4);
                uint32_t adh = sb + ASM_Q + row * 256 + (((uh ^ row) & 7) << 4);
                LDMATRIX_X4(ah[0], ah[1], ah[2], ah[3], adh);
                int ul = 8 + 2 * u + (lane >> 4);
                uint32_t adl = sb + ASM_Q + row * 256 + ((8 | ((ul ^ row) & 7)) << 4);
                LDMATRIX_X4(al[0], al[1], al[2], al[3], adl);
            }
#pragma unroll
            for (int fp = 0; fp < 4; fp++) {
                int n = fp * 16 + (lane & 7) + ((lane >> 4) << 3);
                int uh = 2 * u + ((lane >> 3) & 1);
                uint32_t bh_[4], bl_[4];
                uint32_t bdh = sb + ASM_K + n * 256 + (((uh ^ n) & 7) << 4);
                LDMATRIX_X4(bh_[0], bh_[1], bh_[2], bh_[3], bdh);
                int ul = 8 + 2 * u + ((lane >> 3) & 1);
                uint32_t bdl = sb + ASM_K + n * 256 + ((8 | ((ul ^ n) & 7)) << 4);
                LDMATRIX_X4(bl_[0], bl_[1], bl_[2], bl_[3], bdl);
                MMA_BF16(sf[2 * fp + 0], ah, bh_[0], bh_[1]);
                MMA_BF16(sf[2 * fp + 1], ah, bh_[2], bh_[3]);
                MMA_BF16(sf[2 * fp + 0], ah, bl_[0], bl_[1]);
                MMA_BF16(sf[2 * fp + 1], ah, bl_[2], bl_[3]);
                MMA_BF16(sf[2 * fp + 0], al, bh_[0], bh_[1]);
                MMA_BF16(sf[2 * fp + 1], al, bh_[2], bh_[3]);
            }
        }

        const int r0g = q0 + w * 16 + (lane >> 2);
#pragma unroll
        for (int j = 0; j < 8; j++) {
            int dk = k0 + 8 * j + 2 * (lane & 3) - r0g;
            sf[j][0] += bias_h[dk];
            sf[j][1] += bias_h[dk + 1];
            sf[j][2] += bias_h[dk - 8];
            sf[j][3] += bias_h[dk - 7];
        }

        float mt0 = -1e30f, mt1 = -1e30f;
#pragma unroll
        for (int j = 0; j < 8; j++) {
            mt0 = fmaxf(mt0, fmaxf(sf[j][0], sf[j][1]));
            mt1 = fmaxf(mt1, fmaxf(sf[j][2], sf[j][3]));
        }
        mt0 = fmaxf(mt0, __shfl_xor_sync(0xffffffffu, mt0, 1));
        mt0 = fmaxf(mt0, __shfl_xor_sync(0xffffffffu, mt0, 2));
        mt1 = fmaxf(mt1, __shfl_xor_sync(0xffffffffu, mt1, 1));
        mt1 = fmaxf(mt1, __shfl_xor_sync(0xffffffffu, mt1, 2));

        float mn0 = fmaxf(mrow[0], mt0), mn1 = fmaxf(mrow[1], mt1);
        float alpha0 = __expf(mrow[0] - mn0), alpha1 = __expf(mrow[1] - mn1);
        mrow[0] = mn0; mrow[1] = mn1;

        float ls0 = 0.f, ls1 = 0.f;
#pragma unroll
        for (int j = 0; j < 8; j++) {
            sf[j][0] = __expf(sf[j][0] - mn0);
            sf[j][1] = __expf(sf[j][1] - mn0);
            sf[j][2] = __expf(sf[j][2] - mn1);
            sf[j][3] = __expf(sf[j][3] - mn1);
            ls0 += sf[j][0] + sf[j][1];
            ls1 += sf[j][2] + sf[j][3];
        }
        ls0 += __shfl_xor_sync(0xffffffffu, ls0, 1);
        ls0 += __shfl_xor_sync(0xffffffffu, ls0, 2);
        ls1 += __shfl_xor_sync(0xffffffffu, ls1, 1);
        ls1 += __shfl_xor_sync(0xffffffffu, ls1, 2);
        lrow[0] = lrow[0] * alpha0 + ls0;
        lrow[1] = lrow[1] * alpha1 + ls1;
#pragma unroll
        for (int j = 0; j < 8; j++) {
            ofr[j][0] *= alpha0; ofr[j][1] *= alpha0;
            ofr[j][2] *= alpha1; ofr[j][3] *= alpha1;
        }

#pragma unroll
        for (int kk = 0; kk < 4; kk++) {
            uint32_t ph[4], pl[4];
            split2(sf[2 * kk][0],     sf[2 * kk][1],     ph[0], pl[0]);
            split2(sf[2 * kk][2],     sf[2 * kk][3],     ph[1], pl[1]);
            split2(sf[2 * kk + 1][0], sf[2 * kk + 1][1], ph[2], pl[2]);
            split2(sf[2 * kk + 1][2], sf[2 * kk + 1][3], ph[3], pl[3]);
            const int g = lane >> 3;
            const int rowh = kk * 16 + ((g & 1) << 3) + (lane & 7);
            const int rowl = 64 + rowh;
#pragma unroll
            for (int fb = 0; fb < 4; fb++) {
                int unit = fb * 2 + (g >> 1);
                uint32_t bvh[4], bvl[4];
                uint32_t avh = sb + ASM_V + rowh * 128 + ((unit ^ (rowh & 7)) << 4);
                LDMATRIX_X4_T(bvh[0], bvh[1], bvh[2], bvh[3], avh);
                uint32_t avl = sb + ASM_V + rowl * 128 + ((unit ^ (rowl & 7)) << 4);
                LDMATRIX_X4_T(bvl[0], bvl[1], bvl[2], bvl[3], avl);
                MMA_BF16(ofr[2 * fb + 0], ph, bvh[0], bvh[1]);
                MMA_BF16(ofr[2 * fb + 1], ph, bvh[2], bvh[3]);
                MMA_BF16(ofr[2 * fb + 0], ph, bvl[0], bvl[1]);
                MMA_BF16(ofr[2 * fb + 1], ph, bvl[2], bvl[3]);
                MMA_BF16(ofr[2 * fb + 0], pl, bvh[0], bvh[1]);
                MMA_BF16(ofr[2 * fb + 1], pl, bvh[2], bvh[3]);
            }
        }
    }

    const float inv0 = 1.f / lrow[0], inv1 = 1.f / lrow[1];
    const int r0 = q0 + w * 16 + (lane >> 2), r1 = r0 + 8;
    __nv_bfloat16* row0 = out3 + (size_t)(b * T_ + r0) * K3_;
    __nv_bfloat16* row1 = out3 + (size_t)(b * T_ + r1) * K3_;
#pragma unroll
    for (int j = 0; j < 8; j++) {
        int col = h * HS_ + 8 * j + 2 * (lane & 3);
        uint32_t hi, lo;
        split2(ofr[j][0] * inv0, ofr[j][1] * inv0, hi, lo);
        *(uint32_t*)(row0 + col)          = hi;
        *(uint32_t*)(row0 + D_ + col)     = hi;
        *(uint32_t*)(row0 + 2 * D_ + col) = lo;
        split2(ofr[j][2] * inv1, ofr[j][3] * inv1, hi, lo);
        *(uint32_t*)(row1 + col)          = hi;
        *(uint32_t*)(row1 + D_ + col)     = hi;
        *(uint32_t*)(row1 + 2 * D_ + col) = lo;
    }
}

// ================== launch ==================================================
extern "C" void kernel_launch(void* const* d_in, const int* in_sizes, int n_in,
                              void* d_out, int out_size) {
    const float* queries = (const float*)d_in[0];
    const float* Wq      = (const float*)d_in[1];
    const float* Wk      = (const float*)d_in[2];
    const float* Wv      = (const float*)d_in[3];
    const float* Wo      = (const float*)d_in[4];
    const float* rel_emb = (const float*)d_in[5];
    float* out = (float*)d_out;

    __nv_bfloat16 *gA3, *gAO3, *gW3;
    float *gQ, *gK, *gV, *gB;
    cudaGetSymbolAddress((void**)&gA3,  g_A3);
    cudaGetSymbolAddress((void**)&gAO3, g_AO3);
    cudaGetSymbolAddress((void**)&gW3,  g_W3);
    cudaGetSymbolAddress((void**)&gQ,   g_Q);
    cudaGetSymbolAddress((void**)&gK,   g_K);
    cudaGetSymbolAddress((void**)&gV,   g_V);
    cudaGetSymbolAddress((void**)&gB,   g_bias);

    cudaFuncSetAttribute(attn_hmma,  cudaFuncAttributeMaxDynamicSharedMemorySize, ATTN_SMEM);
    cudaFuncSetAttribute(gemm_hmma3, cudaFuncAttributeMaxDynamicSharedMemorySize, GEMM3_SMEM);

    bias_kernel<<<(NH_ * NBIAS + 255) / 256, 256>>>(rel_emb, gB);
    split3_kernel<0><<<(M_ * (D_ / 4) + 255) / 256, 256>>>(queries, gA3, M_);
    split3_kernel<1><<<(D_ * (D_ / 4) + 255) / 256, 256>>>(Wq, gW3 + 0 * WOFF, D_);
    split3_kernel<1><<<(D_ * (D_ / 4) + 255) / 256, 256>>>(Wk, gW3 + 1 * WOFF, D_);
    split3_kernel<1><<<(D_ * (D_ / 4) + 255) / 256, 256>>>(Wv, gW3 + 2 * WOFF, D_);
    split3_kernel<1><<<(D_ * (D_ / 4) + 255) / 256, 256>>>(Wo, gW3 + 3 * WOFF, D_);

    // fused Q/K/V projections (grid.z picks weight + output)
    dim3 gGrid(D_ / 128, M_ / 128, 3);
    gemm_hmma3<<<gGrid, 256, GEMM3_SMEM>>>(gA3, gW3, gQ, gK, gV);

    // attention -> split AO3 directly
    dim3 aGrid(T_ / QT, B_ * NH_);
    attn_hmma<<<aGrid, 256, ATTN_SMEM>>>(gQ, gK, gV, gB, gAO3);

    // output projection
    dim3 oGrid(D_ / 128, M_ / 128, 1);
    gemm_hmma3<<<oGrid, 256, GEMM3_SMEM>>>(gAO3, gW3 + 3 * WOFF, out, out, out);
}

// round 7
// speedup vs baseline: 3.4166x; 1.0885x over previous
#include <cuda_runtime.h>
#include <cuda_bf16.h>
#include <math.h>
#include <stdint.h>

#define B_  4
#define T_  2048
#define D_  1024
#define NH_ 16
#define HS_ 64
#define NBIAS (2*T_ - 1)   // 4095
#define M_  (B_*T_)        // 8192
#define K2_ 2048           // split-bf16 storage: [hi | lo]

// ---------------- scratch (device globals: no allocation allowed) ----------
__device__ __nv_bfloat16 g_A2 [M_*(size_t)K2_];    // queries split [hi|lo]
__device__ __nv_bfloat16 g_AO2[M_*(size_t)K2_];    // attn-out split [hi|lo]
__device__ __nv_bfloat16 g_W2 [4*(size_t)D_*K2_];  // weights split [hi|lo]
__device__ float g_Q [M_*(size_t)D_];              // row-major [b*t, d]
__device__ float g_K [M_*(size_t)D_];
__device__ float g_V [M_*(size_t)D_];
__device__ float g_bias[NH_*NBIAS];

// ============================ PTX helpers ==================================
__device__ __forceinline__ uint32_t smem_u32(const void* p) {
    uint32_t a;
    asm("{ .reg .u64 t; cvta.to.shared.u64 t, %1; cvt.u32.u64 %0, t; }" : "=r"(a) : "l"(p));
    return a;
}
#define CP_ASYNC16(dst, src) \
    asm volatile("cp.async.cg.shared.global [%0], [%1], 16;" :: "r"(dst), "l"(src) : "memory")
#define CP_COMMIT() asm volatile("cp.async.commit_group;" ::: "memory")
#define CP_WAIT1()  asm volatile("cp.async.wait_group 1;" ::: "memory")

#define LDMATRIX_X4(r0, r1, r2, r3, addr) \
    asm volatile("ldmatrix.sync.aligned.m8n8.x4.shared.b16 {%0,%1,%2,%3}, [%4];" \
                 : "=r"(r0), "=r"(r1), "=r"(r2), "=r"(r3) : "r"(addr))
#define LDMATRIX_X4_T(r0, r1, r2, r3, addr) \
    asm volatile("ldmatrix.sync.aligned.m8n8.x4.trans.shared.b16 {%0,%1,%2,%3}, [%4];" \
                 : "=r"(r0), "=r"(r1), "=r"(r2), "=r"(r3) : "r"(addr))

#define MMA_BF16(c, a, b0, b1) \
    asm volatile("mma.sync.aligned.m16n8k16.row.col.f32.bf16.bf16.f32 " \
                 "{%0,%1,%2,%3}, {%4,%5,%6,%7}, {%8,%9}, {%0,%1,%2,%3};" \
                 : "+f"((c)[0]), "+f"((c)[1]), "+f"((c)[2]), "+f"((c)[3]) \
                 : "r"((a)[0]), "r"((a)[1]), "r"((a)[2]), "r"((a)[3]), "r"(b0), "r"(b1))

__device__ __forceinline__ void split2(float a, float b, uint32_t& hi, uint32_t& lo) {
    __nv_bfloat16 ha = __float2bfloat16_rn(a), hb = __float2bfloat16_rn(b);
    float la = a - __bfloat162float(ha), lb = b - __bfloat162float(hb);
    __nv_bfloat162 hv = __halves2bfloat162(ha, hb);
    __nv_bfloat162 lv = __halves2bfloat162(__float2bfloat16_rn(la), __float2bfloat16_rn(lb));
    hi = *(uint32_t*)&hv;
    lo = *(uint32_t*)&lv;
}

// ================== bias table =============================================
__device__ __forceinline__ int bucket_of(int rp) {
    int b = (rp > 0) ? 16 : 0;
    int a = rp < 0 ? -rp : rp;
    if (a < 8) return b + a;
    double v = 7.0 + (log((double)a / 7.0) / log(128.0 / 7.0)) * 8.0;
    int large = (int)v;
    if (large > 15) large = 15;
    return b + large;
}
__global__ void bias_kernel(const float* __restrict__ rel_emb, float* __restrict__ btab) {
    int idx = blockIdx.x * blockDim.x + threadIdx.x;
    if (idx >= NH_ * NBIAS) return;
    int h = idx / NBIAS;
    int x = idx % NBIAS;
    btab[idx] = rel_emb[bucket_of(x - (T_ - 1)) * NH_ + h];
}

// ================== fp32 -> [hi | lo] split-bf16 ===========================
__global__ void split2_kernel(const float* __restrict__ in, __nv_bfloat16* __restrict__ out,
                              int nrows) {
    int i = blockIdx.x * blockDim.x + threadIdx.x;
    if (i >= nrows * (D_ / 4)) return;
    int r = i / (D_ / 4);
    int c = (i % (D_ / 4)) * 4;
    float4 v = *(const float4*)(in + (size_t)r * D_ + c);
    uint32_t h0, l0, h1, l1;
    split2(v.x, v.y, h0, l0);
    split2(v.z, v.w, h1, l1);
    uint32_t* sh = (uint32_t*)(out + (size_t)r * K2_ + c);
    sh[0] = h0; sh[1] = h1;
    uint32_t* sl = (uint32_t*)(out + (size_t)r * K2_ + D_ + c);
    sl[0] = l0; sl[1] = l1;
}

// ================== HMMA bf16 GEMM v4 (operand reuse) ======================
// out[m,n] = sum_{k<1024} Ah*Bh + Ah*Bl + Al*Bh  (each bf16 pair from [hi|lo])
// CTA 128x128, 8 warps (warp tile 64x32), K loop = 32 iters of BK=32.
// Stage = {Ah, Al, Bh, Bl} tiles (4 x 8KB = 32KB); 3 stages = 96KB, 2 CTA/SM.
#define GS4 3
#define TB4 8192
#define ST4 (4 * TB4)               // 32KB per stage
#define GEMM4_SMEM (GS4 * ST4)      // 96KB
#define GIT4 32
#define WOFF2 ((size_t)D_ * K2_)

__global__ __launch_bounds__(256, 2)
void gemm_hmma4(const __nv_bfloat16* __restrict__ A, const __nv_bfloat16* __restrict__ W0,
                float* __restrict__ o0, float* __restrict__ o1, float* __restrict__ o2) {
    extern __shared__ char sm4[];
    const uint32_t sb = smem_u32(sm4);

    const int tid  = threadIdx.x;
    const int w    = tid >> 5;
    const int lane = tid & 31;
    const int wm   = w & 1;            // 64-row half
    const int wn   = w >> 1;           // 32-col quarter
    const int m0   = blockIdx.y * 128;
    const int n0   = blockIdx.x * 128;
    const int z    = blockIdx.z;
    const __nv_bfloat16* W = W0 + (size_t)z * WOFF2;
    float* out = (z == 0) ? o0 : (z == 1) ? o1 : o2;

    float acc[4][4][4];
#pragma unroll
    for (int i = 0; i < 4; i++)
#pragma unroll
        for (int j = 0; j < 4; j++)
#pragma unroll
            for (int q = 0; q < 4; q++) acc[i][j][q] = 0.f;

    // loader: stage it -> slot it%3; 4 tiles, 2 units each per thread
    auto load_stage = [&](int it) {
        const uint32_t st = sb + (uint32_t)(it % GS4) * ST4;
        const int kb = it * 32;
#pragma unroll
        for (int j = 0; j < 2; j++) {
            int idx = tid * 2 + j;
            int row = idx >> 2, u = idx & 3;
            uint32_t off = row * 64 + ((u ^ ((row >> 1) & 3)) << 4);
            const __nv_bfloat16* ar = A + (size_t)(m0 + row) * K2_ + kb + u * 8;
            const __nv_bfloat16* wr = W + (size_t)(n0 + row) * K2_ + kb + u * 8;
            CP_ASYNC16(st + off,           (const void*)ar);          // Ah
            CP_ASYNC16(st + TB4 + off,     (const void*)(ar + D_));   // Al
            CP_ASYNC16(st + 2 * TB4 + off, (const void*)wr);          // Bh
            CP_ASYNC16(st + 3 * TB4 + off, (const void*)(wr + D_));   // Bl
        }
        CP_COMMIT();
    };

    load_stage(0);
    load_stage(1);

    for (int it = 0; it < GIT4; it++) {
        CP_WAIT1();                      // <=1 group pending -> stage it complete
        __syncthreads();                 // guards slot (it+2)%3 == (it-1)%3 overwrite
        if (it + 2 < GIT4) load_stage(it + 2);
        else CP_COMMIT();

        const uint32_t aH = sb + (uint32_t)(it % GS4) * ST4;
        const uint32_t aL = aH + TB4;
        const uint32_t bH = aH + 2 * TB4;
        const uint32_t bL = aH + 3 * TB4;

#pragma unroll
        for (int ks = 0; ks < 2; ks++) {
            uint32_t ah[4][4], al[4][4];
#pragma unroll
            for (int fm = 0; fm < 4; fm++) {
                int row = wm * 64 + fm * 16 + (lane & 15);
                int u = ks * 2 + (lane >> 4);
                uint32_t off = row * 64 + ((u ^ ((row >> 1) & 3)) << 4);
                LDMATRIX_X4(ah[fm][0], ah[fm][1], ah[fm][2], ah[fm][3], aH + off);
                LDMATRIX_X4(al[fm][0], al[fm][1], al[fm][2], al[fm][3], aL + off);
            }
            uint32_t bh[2][4], bl[2][4];
#pragma unroll
            for (int fp = 0; fp < 2; fp++) {
                int n = wn * 32 + fp * 16 + (lane & 7) + ((lane >> 4) << 3);
                int u = ks * 2 + ((lane >> 3) & 1);
                uint32_t off = n * 64 + ((u ^ ((n >> 1) & 3)) << 4);
                LDMATRIX_X4(bh[fp][0], bh[fp][1], bh[fp][2], bh[fp][3], bH + off);
                LDMATRIX_X4(bl[fp][0], bl[fp][1], bl[fp][2], bl[fp][3], bL + off);
            }
#pragma unroll
            for (int fm = 0; fm < 4; fm++)
#pragma unroll
                for (int fp = 0; fp < 2; fp++) {
                    MMA_BF16(acc[fm][fp * 2 + 0], ah[fm], bh[fp][0], bh[fp][1]);
                    MMA_BF16(acc[fm][fp * 2 + 1], ah[fm], bh[fp][2], bh[fp][3]);
                    MMA_BF16(acc[fm][fp * 2 + 0], ah[fm], bl[fp][0], bl[fp][1]);
                    MMA_BF16(acc[fm][fp * 2 + 1], ah[fm], bl[fp][2], bl[fp][3]);
                    MMA_BF16(acc[fm][fp * 2 + 0], al[fm], bh[fp][0], bh[fp][1]);
                    MMA_BF16(acc[fm][fp * 2 + 1], al[fm], bh[fp][2], bh[fp][3]);
                }
        }
    }

    const int cr = lane >> 2;
    const int cc = 2 * (lane & 3);
#pragma unroll
    for (int fm = 0; fm < 4; fm++) {
        int r = m0 + wm * 64 + fm * 16 + cr;
#pragma unroll
        for (int fn = 0; fn < 4; fn++) {
            int col = n0 + wn * 32 + fn * 8 + cc;
            *(float2*)(out + (size_t)r * D_ + col) =
                make_float2(acc[fm][fn][0], acc[fm][fn][1]);
            *(float2*)(out + (size_t)(r + 8) * D_ + col) =
                make_float2(acc[fm][fn][2], acc[fm][fn][3]);
        }
    }
}

// ================== HMMA flash attention ===================================
#define QT 128
#define KT 64
#define ASM_Q 0u
#define ASM_K 32768u
#define ASM_V 49152u
#define ATTN_SMEM 65536

__global__ __launch_bounds__(256, 2)
void attn_hmma(const float* __restrict__ Q, const float* __restrict__ K,
               const float* __restrict__ V, const float* __restrict__ btab,
               __nv_bfloat16* __restrict__ out2) {
    extern __shared__ char sm[];
    const uint32_t sb = smem_u32(sm);

    const int tid  = threadIdx.x;
    const int w    = tid >> 5;
    const int lane = tid & 31;
    const int bh = blockIdx.y;
    const int h  = bh & (NH_ - 1);
    const int b  = bh >> 4;
    const int q0 = blockIdx.x * QT;

    const float* Qb = Q + (size_t)b * T_ * D_ + h * HS_;
    const float* Kb = K + (size_t)b * T_ * D_ + h * HS_;
    const float* Vb = V + (size_t)b * T_ * D_ + h * HS_;
    const float* bias_h = btab + h * NBIAS + (T_ - 1);

#pragma unroll
    for (int i = tid; i < QT * 16; i += 256) {
        int row = i >> 4, g = i & 15;
        float4 v = *(const float4*)(Qb + (size_t)(q0 + row) * D_ + 4 * g);
        uint32_t h0, l0, h1, l1;
        split2(v.x * 0.125f, v.y * 0.125f, h0, l0);
        split2(v.z * 0.125f, v.w * 0.125f, h1, l1);
        char* rp = sm + ASM_Q + row * 256;
        int su0 = ((g >> 1) ^ row) & 7;
        *(uint32_t*)(rp + su0 * 16 + ((8 * g) & 15))     = h0;
        *(uint32_t*)(rp + su0 * 16 + ((8 * g + 4) & 15)) = h1;
        int su1 = 8 | (((8 + (g >> 1)) ^ row) & 7);
        *(uint32_t*)(rp + su1 * 16 + ((8 * g) & 15))     = l0;
        *(uint32_t*)(rp + su1 * 16 + ((8 * g + 4) & 15)) = l1;
    }

    float ofr[8][4];
    float mrow[2] = {-1e30f, -1e30f};
    float lrow[2] = {0.f, 0.f};
#pragma unroll
    for (int j = 0; j < 8; j++)
#pragma unroll
        for (int q = 0; q < 4; q++) ofr[j][q] = 0.f;

    for (int k0 = 0; k0 < T_; k0 += KT) {
        __syncthreads();
#pragma unroll
        for (int i = tid; i < KT * 16; i += 256) {
            int row = i >> 4, g = i & 15;
            float4 v = *(const float4*)(Kb + (size_t)(k0 + row) * D_ + 4 * g);
            uint32_t h0, l0, h1, l1;
            split2(v.x, v.y, h0, l0);
            split2(v.z, v.w, h1, l1);
            char* rp = sm + ASM_K + row * 256;
            int su0 = ((g >> 1) ^ row) & 7;
            *(uint32_t*)(rp + su0 * 16 + ((8 * g) & 15))     = h0;
            *(uint32_t*)(rp + su0 * 16 + ((8 * g + 4) & 15)) = h1;
            int su1 = 8 | (((8 + (g >> 1)) ^ row) & 7);
            *(uint32_t*)(rp + su1 * 16 + ((8 * g) & 15))     = l0;
            *(uint32_t*)(rp + su1 * 16 + ((8 * g + 4) & 15)) = l1;
        }
#pragma unroll
        for (int i = tid; i < KT * 16; i += 256) {
            int key = i >> 4, g = i & 15;
            float4 v = *(const float4*)(Vb + (size_t)(k0 + key) * D_ + 4 * g);
            uint32_t h0, l0, h1, l1;
            split2(v.x, v.y, h0, l0);
            split2(v.z, v.w, h1, l1);
            int u = g >> 1;
            char* rh = sm + ASM_V + key * 128;
            int suh = (u ^ (key & 7));
            *(uint32_t*)(rh + suh * 16 + ((8 * g) & 15))     = h0;
            *(uint32_t*)(rh + suh * 16 + ((8 * g + 4) & 15)) = h1;
            char* rl = sm + ASM_V + (64 + key) * 128;
            *(uint32_t*)(rl + suh * 16 + ((8 * g) & 15))     = l0;
            *(uint32_t*)(rl + suh * 16 + ((8 * g + 4) & 15)) = l1;
        }
        __syncthreads();

        float sf[8][4];
#pragma unroll
        for (int j = 0; j < 8; j++)
#pragma unroll
            for (int q = 0; q < 4; q++) sf[j][q] = 0.f;

#pragma unroll
        for (int u = 0; u < 4; u++) {
            uint32_t ah[4], al[4];
            {
                int row = w * 16 + (lane & 15);
                int uh = 2 * u + (lane >> 4);
                uint32_t adh = sb + ASM_Q + row * 256 + (((uh ^ row) & 7) << 4);
                LDMATRIX_X4(ah[0], ah[1], ah[2], ah[3], adh);
                int ul = 8 + 2 * u + (lane >> 4);
                uint32_t adl = sb + ASM_Q + row * 256 + ((8 | ((ul ^ row) & 7)) << 4);
                LDMATRIX_X4(al[0], al[1], al[2], al[3], adl);
            }
#pragma unroll
            for (int fp = 0; fp < 4; fp++) {
                int n = fp * 16 + (lane & 7) + ((lane >> 4) << 3);
                int uh = 2 * u + ((lane >> 3) & 1);
                uint32_t bh_[4], bl_[4];
                uint32_t bdh = sb + ASM_K + n * 256 + (((uh ^ n) & 7) << 4);
                LDMATRIX_X4(bh_[0], bh_[1], bh_[2], bh_[3], bdh);
                int ul = 8 + 2 * u + ((lane >> 3) & 1);
                uint32_t bdl = sb + ASM_K + n * 256 + ((8 | ((ul ^ n) & 7)) << 4);
                LDMATRIX_X4(bl_[0], bl_[1], bl_[2], bl_[3], bdl);
                MMA_BF16(sf[2 * fp + 0], ah, bh_[0], bh_[1]);
                MMA_BF16(sf[2 * fp + 1], ah, bh_[2], bh_[3]);
                MMA_BF16(sf[2 * fp + 0], ah, bl_[0], bl_[1]);
                MMA_BF16(sf[2 * fp + 1], ah, bl_[2], bl_[3]);
                MMA_BF16(sf[2 * fp + 0], al, bh_[0], bh_[1]);
                MMA_BF16(sf[2 * fp + 1], al, bh_[2], bh_[3]);
            }
        }

        const int r0g = q0 + w * 16 + (lane >> 2);
#pragma unroll
        for (int j = 0; j < 8; j++) {
            int dk = k0 + 8 * j + 2 * (lane & 3) - r0g;
            sf[j][0] += bias_h[dk];
            sf[j][1] += bias_h[dk + 1];
            sf[j][2] += bias_h[dk - 8];
            sf[j][3] += bias_h[dk - 7];
        }

        float mt0 = -1e30f, mt1 = -1e30f;
#pragma unroll
        for (int j = 0; j < 8; j++) {
            mt0 = fmaxf(mt0, fmaxf(sf[j][0], sf[j][1]));
            mt1 = fmaxf(mt1, fmaxf(sf[j][2], sf[j][3]));
        }
        mt0 = fmaxf(mt0, __shfl_xor_sync(0xffffffffu, mt0, 1));
        mt0 = fmaxf(mt0, __shfl_xor_sync(0xffffffffu, mt0, 2));
        mt1 = fmaxf(mt1, __shfl_xor_sync(0xffffffffu, mt1, 1));
        mt1 = fmaxf(mt1, __shfl_xor_sync(0xffffffffu, mt1, 2));

        float mn0 = fmaxf(mrow[0], mt0), mn1 = fmaxf(mrow[1], mt1);
        float alpha0 = __expf(mrow[0] - mn0), alpha1 = __expf(mrow[1] - mn1);
        mrow[0] = mn0; mrow[1] = mn1;

        float ls0 = 0.f, ls1 = 0.f;
#pragma unroll
        for (int j = 0; j < 8; j++) {
            sf[j][0] = __expf(sf[j][0] - mn0);
            sf[j][1] = __expf(sf[j][1] - mn0);
            sf[j][2] = __expf(sf[j][2] - mn1);
            sf[j][3] = __expf(sf[j][3] - mn1);
            ls0 += sf[j][0] + sf[j][1];
            ls1 += sf[j][2] + sf[j][3];
        }
        ls0 += __shfl_xor_sync(0xffffffffu, ls0, 1);
        ls0 += __shfl_xor_sync(0xffffffffu, ls0, 2);
        ls1 += __shfl_xor_sync(0xffffffffu, ls1, 1);
        ls1 += __shfl_xor_sync(0xffffffffu, ls1, 2);
        lrow[0] = lrow[0] * alpha0 + ls0;
        lrow[1] = lrow[1] * alpha1 + ls1;
#pragma unroll
        for (int j = 0; j < 8; j++) {
            ofr[j][0] *= alpha0; ofr[j][1] *= alpha0;
            ofr[j][2] *= alpha1; ofr[j][3] *= alpha1;
        }

#pragma unroll
        for (int kk = 0; kk < 4; kk++) {
            uint32_t ph[4], pl[4];
            split2(sf[2 * kk][0],     sf[2 * kk][1],     ph[0], pl[0]);
            split2(sf[2 * kk][2],     sf[2 * kk][3],     ph[1], pl[1]);
            split2(sf[2 * kk + 1][0], sf[2 * kk + 1][1], ph[2], pl[2]);
            split2(sf[2 * kk + 1][2], sf[2 * kk + 1][3], ph[3], pl[3]);
            const int g = lane >> 3;
            const int rowh = kk * 16 + ((g & 1) << 3) + (lane & 7);
            const int rowl = 64 + rowh;
#pragma unroll
            for (int fb = 0; fb < 4; fb++) {
                int unit = fb * 2 + (g >> 1);
                uint32_t bvh[4], bvl[4];
                uint32_t avh = sb + ASM_V + rowh * 128 + ((unit ^ (rowh & 7)) << 4);
                LDMATRIX_X4_T(bvh[0], bvh[1], bvh[2], bvh[3], avh);
                uint32_t avl = sb + ASM_V + rowl * 128 + ((unit ^ (rowl & 7)) << 4);
                LDMATRIX_X4_T(bvl[0], bvl[1], bvl[2], bvl[3], avl);
                MMA_BF16(ofr[2 * fb + 0], ph, bvh[0], bvh[1]);
                MMA_BF16(ofr[2 * fb + 1], ph, bvh[2], bvh[3]);
                MMA_BF16(ofr[2 * fb + 0], ph, bvl[0], bvl[1]);
                MMA_BF16(ofr[2 * fb + 1], ph, bvl[2], bvl[3]);
                MMA_BF16(ofr[2 * fb + 0], pl, bvh[0], bvh[1]);
                MMA_BF16(ofr[2 * fb + 1], pl, bvh[2], bvh[3]);
            }
        }
    }

    // ---- epilogue: write split-bf16 AO2 directly ([hi | lo]) ----
    const float inv0 = 1.f / lrow[0], inv1 = 1.f / lrow[1];
    const int r0 = q0 + w * 16 + (lane >> 2), r1 = r0 + 8;
    __nv_bfloat16* row0 = out2 + (size_t)(b * T_ + r0) * K2_;
    __nv_bfloat16* row1 = out2 + (size_t)(b * T_ + r1) * K2_;
#pragma unroll
    for (int j = 0; j < 8; j++) {
        int col = h * HS_ + 8 * j + 2 * (lane & 3);
        uint32_t hi, lo;
        split2(ofr[j][0] * inv0, ofr[j][1] * inv0, hi, lo);
        *(uint32_t*)(row0 + col)      = hi;
        *(uint32_t*)(row0 + D_ + col) = lo;
        split2(ofr[j][2] * inv1, ofr[j][3] * inv1, hi, lo);
        *(uint32_t*)(row1 + col)      = hi;
        *(uint32_t*)(row1 + D_ + col) = lo;
    }
}

// ================== launch ==================================================
extern "C" void kernel_launch(void* const* d_in, const int* in_sizes, int n_in,
                              void* d_out, int out_size) {
    const float* queries = (const float*)d_in[0];
    const float* Wq      = (const float*)d_in[1];
    const float* Wk      = (const float*)d_in[2];
    const float* Wv      = (const float*)d_in[3];
    const float* Wo      = (const float*)d_in[4];
    const float* rel_emb = (const float*)d_in[5];
    float* out = (float*)d_out;

    __nv_bfloat16 *gA2, *gAO2, *gW2;
    float *gQ, *gK, *gV, *gB;
    cudaGetSymbolAddress((void**)&gA2,  g_A2);
    cudaGetSymbolAddress((void**)&gAO2, g_AO2);
    cudaGetSymbolAddress((void**)&gW2,  g_W2);
    cudaGetSymbolAddress((void**)&gQ,   g_Q);
    cudaGetSymbolAddress((void**)&gK,   g_K);
    cudaGetSymbolAddress((void**)&gV,   g_V);
    cudaGetSymbolAddress((void**)&gB,   g_bias);

    cudaFuncSetAttribute(attn_hmma,  cudaFuncAttributeMaxDynamicSharedMemorySize, ATTN_SMEM);
    cudaFuncSetAttribute(gemm_hmma4, cudaFuncAttributeMaxDynamicSharedMemorySize, GEMM4_SMEM);

    // launches 1-5: splits  (ncu -s 5 -c 1 will capture launch #6 = QKV GEMM)
    split2_kernel<<<(M_ * (D_ / 4) + 255) / 256, 256>>>(queries, gA2, M_);
    split2_kernel<<<(D_ * (D_ / 4) + 255) / 256, 256>>>(Wq, gW2 + 0 * WOFF2, D_);
    split2_kernel<<<(D_ * (D_ / 4) + 255) / 256, 256>>>(Wk, gW2 + 1 * WOFF2, D_);
    split2_kernel<<<(D_ * (D_ / 4) + 255) / 256, 256>>>(Wv, gW2 + 2 * WOFF2, D_);
    split2_kernel<<<(D_ * (D_ / 4) + 255) / 256, 256>>>(Wo, gW2 + 3 * WOFF2, D_);

    // launch 6: fused Q/K/V projections
    dim3 gGrid(D_ / 128, M_ / 128, 3);
    gemm_hmma4<<<gGrid, 256, GEMM4_SMEM>>>(gA2, gW2, gQ, gK, gV);

    // launch 7: bias table (only needed by attention)
    bias_kernel<<<(NH_ * NBIAS + 255) / 256, 256>>>(rel_emb, gB);

    // launch 8: attention -> split AO2 directly
    dim3 aGrid(T_ / QT, B_ * NH_);
    attn_hmma<<<aGrid, 256, ATTN_SMEM>>>(gQ, gK, gV, gB, gAO2);

    // launch 9: output projection
    dim3 oGrid(D_ / 128, M_ / 128, 1);
    gemm_hmma4<<<oGrid, 256, GEMM4_SMEM>>>(gAO2, gW2 + 3 * WOFF2, out, out, out);
}